// round 15
// baseline (speedup 1.0000x reference)
#include <cuda_runtime.h>
#include <cuda_bf16.h>
#include <cstdint>

#define NN   100000
#define EE   400000
#define GG   2000
#define IND  32
#define HD   192
#define NL   4
#define EPSV 1e-5f

typedef unsigned long long ull;

// ---------------- persistent device scratch -------------------------------
__device__ float g_h[(size_t)NN * HD];
__device__ float g_rel[(size_t)NN * HD];
__device__ float g_agg[(size_t)NN * HD];
__device__ __nv_bfloat16 g_ahi[(size_t)NN * HD];
__device__ __nv_bfloat16 g_alo[(size_t)NN * HD];
__device__ __nv_bfloat16 g_x0hi[(size_t)NN * 64];
__device__ __nv_bfloat16 g_x0lo[(size_t)NN * 64];
__device__ __nv_bfloat16 g_wt0[2 * 2 * 192 * 64];        // [mat][split][192n * 64k]
__device__ __nv_bfloat16 g_wtl[3 * 2 * 2 * 192 * 192];   // [l][mat][split][192n * 192k]
__device__ int   g_deg[NN + 1];
__device__ int   g_rowptr[NN + 1];
__device__ int   g_csrsrc[EE];
__device__ int   g_bsum[128];
__device__ int   g_bsumx[128];
__device__ int   g_cnt[GG];
__device__ int   g_gstart[GG + 1];
__device__ float g_stats[NL * 2 * HD];
__device__ float g_affine[2 * HD];
__device__ float g_pool[(size_t)GG * HD];
__device__ float g_t1[(size_t)GG * HD];
__device__ float g_t2[(size_t)GG * HD];

// ---------------- PTX helpers ----------------------------------------------
__device__ __forceinline__ uint32_t smem_u32(const void* p) {
    uint32_t a;
    asm("{ .reg .u64 t; cvta.to.shared.u64 t, %1; cvt.u32.u64 %0, t; }"
        : "=r"(a) : "l"(p));
    return a;
}

__device__ __forceinline__ void mma_bf16(float* d, const uint32_t* a, const uint32_t* b) {
    asm volatile(
        "mma.sync.aligned.m16n8k16.row.col.f32.bf16.bf16.f32 "
        "{%0,%1,%2,%3}, {%4,%5,%6,%7}, {%8,%9}, {%0,%1,%2,%3};"
        : "+f"(d[0]), "+f"(d[1]), "+f"(d[2]), "+f"(d[3])
        : "r"(a[0]), "r"(a[1]), "r"(a[2]), "r"(a[3]), "r"(b[0]), "r"(b[1]));
}

#define LDSM4(r, addr) \
    asm volatile("ldmatrix.sync.aligned.m8n8.x4.shared.b16 {%0,%1,%2,%3}, [%4];" \
                 : "=r"((r)[0]), "=r"((r)[1]), "=r"((r)[2]), "=r"((r)[3]) : "r"(addr))

__device__ __forceinline__ void cpa16(uint32_t dst, const void* src, int srcBytes) {
    asm volatile("cp.async.cg.shared.global [%0], [%1], 16, %2;"
                 :: "r"(dst), "l"(src), "r"(srcBytes) : "memory");
}
#define CP_COMMIT() asm volatile("cp.async.commit_group;" ::: "memory")
#define CP_WAIT(n)  asm volatile("cp.async.wait_group %0;" :: "n"(n) : "memory")

// ======= GEMM variant 1: streaming, M64xN192, for L0 (K=32) ================
__global__ __launch_bounds__(256, 2) void k_mma_s(
    const __nv_bfloat16* __restrict__ Xhi, const __nv_bfloat16* __restrict__ Xlo,
    int ldA, int K, int M,
    const __nv_bfloat16* __restrict__ B0, const __nv_bfloat16* __restrict__ B1,
    int ldB, const float* __restrict__ bias,
    float* __restrict__ O1, float* __restrict__ O2)
{
    extern __shared__ __nv_bfloat16 sm[];
    const int chunk = (K < 32) ? K : 32;
    const int S = chunk + 8;
    const int tid = threadIdx.x, lane = tid & 31, wid = tid >> 5;
    const int warpM = wid & 1, warpN = wid >> 1;
    const int row0 = blockIdx.x * 64;
    const int mat = blockIdx.y;
    const __nv_bfloat16* Bbase = mat ? B1 : B0;
    const size_t splitOffB = (size_t)192 * ldB;

    const uint32_t sb = smem_u32(sm);
    const uint32_t offAlo   = 64 * S * 2;
    const uint32_t offBh    = 128 * S * 2;
    const uint32_t offBlo   = 192 * S * 2;
    const uint32_t stageSz  = (128 + 384) * S * 2;

    float d[2][6][4];
#pragma unroll
    for (int a = 0; a < 2; a++)
#pragma unroll
        for (int b = 0; b < 6; b++)
#pragma unroll
            for (int c = 0; c < 4; c++) d[a][b][c] = 0.f;

    const uint32_t aAddr = sb +
        (((warpM * 32 + (lane & 15)) * S + ((lane >> 4) * 8)) * 2);
    const uint32_t bAddr = sb + offBh +
        (((warpN * 48 + (lane & 7) + ((lane >> 4) << 3)) * S + (((lane >> 3) & 1) * 8)) * 2);
    const uint32_t step16 = 16 * S * 2;

    const int cv = chunk >> 3;
    const int nChunks = K / chunk;

    auto load_chunk = [&](int c, int stage) {
        const uint32_t st = sb + stage * stageSz;
        const int kc = c * chunk;
        for (int idx = tid; idx < 64 * cv; idx += 256) {
            const int rr = idx / cv, kv = idx % cv;
            const int row = row0 + rr;
            const int ok = (row < M) ? 16 : 0;
            const size_t so = (size_t)(ok ? row : 0) * ldA + kc + kv * 8;
            const uint32_t doff = (rr * S + kv * 8) * 2;
            cpa16(st + doff, Xhi + so, ok);
            cpa16(st + offAlo + doff, Xlo + so, ok);
        }
        for (int idx = tid; idx < 192 * cv; idx += 256) {
            const int nn = idx / cv, kv = idx % cv;
            const __nv_bfloat16* src = Bbase + (size_t)nn * ldB + kc + kv * 8;
            const uint32_t doff = (nn * S + kv * 8) * 2;
            cpa16(st + offBh + doff, src, 16);
            cpa16(st + offBh + offBlo + doff, src + splitOffB, 16);
        }
        CP_COMMIT();
    };

    load_chunk(0, 0);

    for (int c = 0; c < nChunks; c++) {
        const int stage = c & 1;
        if (c + 1 < nChunks) { load_chunk(c + 1, stage ^ 1); CP_WAIT(1); }
        else                 { CP_WAIT(0); }
        __syncthreads();

        const uint32_t so = stage * stageSz;
        const int nk = chunk >> 4;
        for (int ks = 0; ks < nk; ks++) {
            const uint32_t kb = (uint32_t)ks * 32;
            uint32_t ah0[4], al0[4], ah1[4], al1[4];
            LDSM4(ah0, aAddr + so + kb);
            LDSM4(al0, aAddr + so + kb + offAlo);
            LDSM4(ah1, aAddr + so + kb + step16);
            LDSM4(al1, aAddr + so + kb + step16 + offAlo);
#pragma unroll
            for (int p = 0; p < 3; p++) {
                uint32_t bh4[4], bl4[4];
                LDSM4(bh4, bAddr + so + kb + p * step16);
                LDSM4(bl4, bAddr + so + kb + p * step16 + offBlo);
#pragma unroll
                for (int hh = 0; hh < 2; hh++) {
                    const int nj = p * 2 + hh;
                    const uint32_t* b_h = &bh4[hh * 2];
                    const uint32_t* b_l = &bl4[hh * 2];
                    mma_bf16(d[0][nj], ah0, b_h);
                    mma_bf16(d[0][nj], ah0, b_l);
                    mma_bf16(d[0][nj], al0, b_h);
                    mma_bf16(d[1][nj], ah1, b_h);
                    mma_bf16(d[1][nj], ah1, b_l);
                    mma_bf16(d[1][nj], al1, b_h);
                }
            }
        }
        __syncthreads();
    }

    const int r = lane >> 2, cq = lane & 3;
    float* O = mat ? O2 : O1;
#pragma unroll
    for (int nj = 0; nj < 6; nj++) {
        const int col = warpN * 48 + nj * 8 + cq * 2;
        float b0 = 0.f, b1v = 0.f;
        if (mat == 0 && bias) { b0 = bias[col]; b1v = bias[col + 1]; }
#pragma unroll
        for (int mi = 0; mi < 2; mi++) {
            const int rr = row0 + warpM * 32 + mi * 16 + r;
            if (rr < M) {
                float2 v = make_float2(d[mi][nj][0] + b0, d[mi][nj][1] + b1v);
                *(float2*)(&O[(size_t)rr * HD + col]) = v;
            }
            if (rr + 8 < M) {
                float2 v = make_float2(d[mi][nj][2] + b0, d[mi][nj][3] + b1v);
                *(float2*)(&O[(size_t)(rr + 8) * HD + col]) = v;
            }
        }
    }
}

// ======= GEMM variant 2: B-resident + cross-tile prefetch (K=192) ===========
__global__ __launch_bounds__(256, 2) void k_mma_b(
    const __nv_bfloat16* __restrict__ Xhi, const __nv_bfloat16* __restrict__ Xlo,
    int ldA, int K, int M,
    const __nv_bfloat16* __restrict__ B0, const __nv_bfloat16* __restrict__ B1,
    int ldB, const float* __restrict__ bias,
    float* __restrict__ O1, float* __restrict__ O2)
{
    extern __shared__ __nv_bfloat16 sm[];
    const int chunk = (K < 32) ? K : 32;
    const int S = chunk + 8;
    const int SB = K + 8;
    const int tid = threadIdx.x, lane = tid & 31, wid = tid >> 5;
    const int warpM = wid & 3, warpN = wid >> 2;
    const int mat = blockIdx.y >> 1;
    const int ncol0 = (blockIdx.y & 1) * 96;
    const __nv_bfloat16* Bbase = mat ? B1 : B0;
    const size_t splitOffB = (size_t)192 * ldB;

    const uint32_t sb = smem_u32(sm);
    const uint32_t offAlo   = 64 * S * 2;
    const uint32_t stageSz  = 128 * S * 2;
    const uint32_t offB     = 2 * stageSz;
    const uint32_t offBlo   = (uint32_t)(96 * SB * 2);

    // ---- B resident load (once) ----
    const int KV = K >> 3;
    for (int idx = tid; idx < 96 * KV; idx += 256) {
        const int nn = idx / KV, kv = idx % KV;
        const __nv_bfloat16* src = Bbase + (size_t)(ncol0 + nn) * ldB + kv * 8;
        const uint32_t doff = (uint32_t)((nn * SB + kv * 8) * 2);
        cpa16(sb + offB + doff, src, 16);
        cpa16(sb + offB + offBlo + doff, src + splitOffB, 16);
    }
    CP_COMMIT();

    const uint32_t aAddr = sb +
        (((warpM * 16 + (lane & 15)) * S + ((lane >> 4) * 8)) * 2);
    const uint32_t bAddr = sb + offB +
        (uint32_t)((((warpN * 48 + (lane & 7) + ((lane >> 4) << 3)) * SB) +
                    (((lane >> 3) & 1) * 8)) * 2);
    const uint32_t bStep16 = (uint32_t)(16 * SB * 2);

    const int cv = chunk >> 3;
    const int nChunks = K / chunk;     // 6 (even -> chunk0 always stage 0)
    const int nTiles = (M + 63) >> 6;

    const int r = lane >> 2, cq = lane & 3;
    float* O = mat ? O2 : O1;

    auto loadA = [&](int row0, int c, int stage) {
        const uint32_t st = sb + stage * stageSz;
        const int kc = c * chunk;
        for (int idx = tid; idx < 64 * cv; idx += 256) {
            const int rr = idx / cv, kv = idx % cv;
            const int row = row0 + rr;
            const int ok = (row < M) ? 16 : 0;
            const size_t so = (size_t)(ok ? row : 0) * ldA + kc + kv * 8;
            const uint32_t doff = (rr * S + kv * 8) * 2;
            cpa16(st + doff, Xhi + so, ok);
            cpa16(st + offAlo + doff, Xlo + so, ok);
        }
        CP_COMMIT();
    };

    int first = 1;
    for (int mt = blockIdx.x; mt < nTiles; mt += gridDim.x) {
        const int row0 = mt * 64;

        float d[6][4];
#pragma unroll
        for (int b = 0; b < 6; b++)
#pragma unroll
            for (int c = 0; c < 4; c++) d[b][c] = 0.f;

        if (first) { loadA(row0, 0, 0); first = 0; }   // else: prefetched

        for (int c = 0; c < nChunks; c++) {
            const int stage = c & 1;
            int issued = 0;
            if (c + 1 < nChunks) {
                loadA(row0, c + 1, stage ^ 1);
                issued = 1;
            } else {
                const int nmt = mt + gridDim.x;
                if (nmt < nTiles) { loadA(nmt * 64, 0, stage ^ 1); issued = 1; }
            }
            if (issued) CP_WAIT(1); else CP_WAIT(0);
            __syncthreads();

            const uint32_t so = stage * stageSz;
            const int nk = chunk >> 4;
            for (int ks = 0; ks < nk; ks++) {
                const uint32_t kbA = (uint32_t)ks * 32;
                const uint32_t kcol = (uint32_t)((c * chunk + ks * 16) * 2);
                uint32_t ah[4], al[4];
                LDSM4(ah, aAddr + so + kbA);
                LDSM4(al, aAddr + so + kbA + offAlo);
#pragma unroll
                for (int p = 0; p < 3; p++) {
                    uint32_t bh4[4], bl4[4];
                    LDSM4(bh4, bAddr + kcol + p * bStep16);
                    LDSM4(bl4, bAddr + kcol + p * bStep16 + offBlo);
#pragma unroll
                    for (int hh = 0; hh < 2; hh++) {
                        const int nj = p * 2 + hh;
                        const uint32_t* b_h = &bh4[hh * 2];
                        const uint32_t* b_l = &bl4[hh * 2];
                        mma_bf16(d[nj], ah, b_h);
                        mma_bf16(d[nj], ah, b_l);
                        mma_bf16(d[nj], al, b_h);
                    }
                }
            }
            __syncthreads();
        }

#pragma unroll
        for (int nj = 0; nj < 6; nj++) {
            const int col = ncol0 + warpN * 48 + nj * 8 + cq * 2;
            float b0 = 0.f, b1v = 0.f;
            if (mat == 0 && bias) { b0 = bias[col]; b1v = bias[col + 1]; }
            const int rr = row0 + warpM * 16 + r;
            if (rr < M) {
                float2 v = make_float2(d[nj][0] + b0, d[nj][1] + b1v);
                *(float2*)(&O[(size_t)rr * HD + col]) = v;
            }
            if (rr + 8 < M) {
                float2 v = make_float2(d[nj][2] + b0, d[nj][3] + b1v);
                *(float2*)(&O[(size_t)(rr + 8) * HD + col]) = v;
            }
        }
    }
}

// ---------------- weight / activation prep ----------------------------------
__device__ __forceinline__ void split_bf16(float v, __nv_bfloat16& h, __nv_bfloat16& l) {
    h = __float2bfloat16(v);
    l = __float2bfloat16(v - __bfloat162float(h));
}
__device__ __forceinline__ uint32_t pk_bf16(__nv_bfloat16 a, __nv_bfloat16 b) {
    __nv_bfloat162 t(a, b);
    return *reinterpret_cast<uint32_t*>(&t);
}

__global__ void k_prep_w(const float* __restrict__ Wrel0, const float* __restrict__ Wroot0,
                         const float* __restrict__ Wrel, const float* __restrict__ Wroot,
                         __nv_bfloat16* wt0, __nv_bfloat16* wtl)
{
    int i = blockIdx.x * blockDim.x + threadIdx.x;
    if (i < 2 * 192 * 64) {
        int mat = i / (192 * 64), r = i % (192 * 64);
        int n = r / 64, k = r % 64;
        const float* W = mat ? Wroot0 : Wrel0;
        float v = (k < IND) ? W[k * HD + n] : 0.f;
        __nv_bfloat16 h, l; split_bf16(v, h, l);
        wt0[mat * (2 * 192 * 64) + r] = h;
        wt0[mat * (2 * 192 * 64) + 192 * 64 + r] = l;
    }
    if (i < 3 * 2 * 192 * 192) {
        int ly = i / (2 * 192 * 192), r1 = i % (2 * 192 * 192);
        int mat = r1 / (192 * 192), r = r1 % (192 * 192);
        int n = r / 192, k = r % 192;
        const float* W = (mat ? Wroot : Wrel) + (size_t)ly * HD * HD;
        float v = W[k * HD + n];
        __nv_bfloat16 h, l; split_bf16(v, h, l);
        wtl[(size_t)((ly * 2 + mat) * 2 + 0) * (192 * 192) + r] = h;
        wtl[(size_t)((ly * 2 + mat) * 2 + 1) * (192 * 192) + r] = l;
    }
}

// input split + zero deg/cnt/stats (folded zero_csr)
__global__ void k_conv_x0(const float* __restrict__ x,
                          __nv_bfloat16* __restrict__ xhi, __nv_bfloat16* __restrict__ xlo,
                          int* deg, int* cnt, float* stats)
{
    size_t i = (size_t)blockIdx.x * blockDim.x + threadIdx.x;
    if (i < NN) deg[i] = 0;
    if (i < GG) cnt[i] = 0;
    if (i < NL * 2 * HD) stats[i] = 0.f;
    if (i >= (size_t)NN * 8) return;
    const int row = (int)(i >> 3), oct = (int)(i & 7);
    __nv_bfloat16 h[8], l[8];
    if (oct < 4) {
        const float4 v0 = *(const float4*)(x + (size_t)row * IND + oct * 8);
        const float4 v1 = *(const float4*)(x + (size_t)row * IND + oct * 8 + 4);
        split_bf16(v0.x, h[0], l[0]); split_bf16(v0.y, h[1], l[1]);
        split_bf16(v0.z, h[2], l[2]); split_bf16(v0.w, h[3], l[3]);
        split_bf16(v1.x, h[4], l[4]); split_bf16(v1.y, h[5], l[5]);
        split_bf16(v1.z, h[6], l[6]); split_bf16(v1.w, h[7], l[7]);
    } else {
#pragma unroll
        for (int k = 0; k < 8; k++) { h[k] = __float2bfloat16(0.f); l[k] = h[k]; }
    }
    uint4 hv = make_uint4(pk_bf16(h[0], h[1]), pk_bf16(h[2], h[3]),
                          pk_bf16(h[4], h[5]), pk_bf16(h[6], h[7]));
    uint4 lv = make_uint4(pk_bf16(l[0], l[1]), pk_bf16(l[2], l[3]),
                          pk_bf16(l[4], l[5]), pk_bf16(l[6], l[7]));
    *(uint4*)(xhi + (size_t)row * 64 + oct * 8) = hv;
    *(uint4*)(xlo + (size_t)row * 64 + oct * 8) = lv;
}

// relu(a*h + b) -> bf16 hi/lo, affine computed in-kernel from stats (fused BN)
__global__ void k_act_conv(const float* __restrict__ h,
                           const float* __restrict__ stats,
                           const float* __restrict__ gamma,
                           const float* __restrict__ beta, int l,
                           __nv_bfloat16* __restrict__ ahi, __nv_bfloat16* __restrict__ alo)
{
    size_t i = (size_t)blockIdx.x * blockDim.x + threadIdx.x;
    if (i >= (size_t)NN * 48) return;
    const int f4 = (int)(i % 48);
    const int f = f4 * 4;
    const float inv = 1.f / (float)NN;
    float a4[4], b4[4];
#pragma unroll
    for (int k = 0; k < 4; k++) {
        const float mu = stats[f + k] * inv;
        const float var = stats[HD + f + k] * inv - mu * mu;
        const float a = gamma[l * HD + f + k] * rsqrtf(var + EPSV);
        a4[k] = a;
        b4[k] = fmaf(-mu, a, beta[l * HD + f + k]);
    }
    const float4 v = *(const float4*)(h + i * 4);
    float x0 = fmaxf(fmaf(v.x, a4[0], b4[0]), 0.f);
    float x1 = fmaxf(fmaf(v.y, a4[1], b4[1]), 0.f);
    float x2 = fmaxf(fmaf(v.z, a4[2], b4[2]), 0.f);
    float x3 = fmaxf(fmaf(v.w, a4[3], b4[3]), 0.f);
    __nv_bfloat16 h0, h1, h2, h3, l0, l1, l2, l3;
    split_bf16(x0, h0, l0); split_bf16(x1, h1, l1);
    split_bf16(x2, h2, l2); split_bf16(x3, h3, l3);
    *(uint2*)(ahi + i * 4) = make_uint2(pk_bf16(h0, h1), pk_bf16(h2, h3));
    *(uint2*)(alo + i * 4) = make_uint2(pk_bf16(l0, l1), pk_bf16(l2, l3));
}

// ---------------- CSR build ---------------------------------------------------
__global__ void k_count(const int* __restrict__ dst, const int* __restrict__ batch,
                        int* deg, int* cnt) {
    int i = blockIdx.x * blockDim.x + threadIdx.x;
    if (i < EE) atomicAdd(&deg[dst[i]], 1);
    if (i < NN) atomicAdd(&cnt[batch[i]], 1);
}
__global__ void k_scan_block(const int* __restrict__ in, int* rowptr, int* bsum) {
    __shared__ int s[1024];
    int t = threadIdx.x;
    int i = blockIdx.x * 1024 + t;
    int v = (i < NN) ? in[i] : 0;
    s[t] = v;
    __syncthreads();
#pragma unroll
    for (int off = 1; off < 1024; off <<= 1) {
        int add = (t >= off) ? s[t - off] : 0;
        __syncthreads();
        s[t] += add;
        __syncthreads();
    }
    if (i < NN) rowptr[i + 1] = s[t];
    if (t == 1023) bsum[blockIdx.x] = s[1023];
}
__global__ void k_scan_single(const int* __restrict__ in, int* out, int n, int writeTotal) {
    __shared__ int s[1024];
    __shared__ int carry;
    int t = threadIdx.x;
    if (t == 0) carry = 0;
    __syncthreads();
    for (int c0 = 0; c0 < n; c0 += 1024) {
        int v = (c0 + t < n) ? in[c0 + t] : 0;
        s[t] = v;
        __syncthreads();
#pragma unroll
        for (int off = 1; off < 1024; off <<= 1) {
            int add = (t >= off) ? s[t - off] : 0;
            __syncthreads();
            s[t] += add;
            __syncthreads();
        }
        if (c0 + t < n) out[c0 + t] = carry + s[t] - v;
        __syncthreads();
        if (t == 1023) carry += s[1023];
        __syncthreads();
    }
    if (t == 0 && writeTotal) out[n] = carry;
}
// fix rowptr (add block prefix) AND write the fill cursor (folded copy_cursor)
__global__ void k_scan_fix(int* rowptr, const int* __restrict__ bsumx, int* cursor) {
    int i = blockIdx.x * 1024 + threadIdx.x;
    if (i < NN) {
        const int v = rowptr[i + 1] + bsumx[blockIdx.x];
        rowptr[i + 1] = v;
        if (i + 1 < NN) cursor[i + 1] = v;
    }
    if (i == 0) { rowptr[0] = 0; cursor[0] = 0; }
}
__global__ void k_fill(const int* __restrict__ src, const int* __restrict__ dst,
                       int* cursor, int* csrsrc) {
    int i = blockIdx.x * blockDim.x + threadIdx.x;
    if (i < EE) {
        int slot = atomicAdd(&cursor[dst[i]], 1);
        csrsrc[slot] = src[i];
    }
}

// ---------------- fused aggregate + BN stats (float2, 96-thr warp-aligned) ---
__global__ __launch_bounds__(192) void k_aggstats(
    const float* __restrict__ relf, const float* __restrict__ rootf,
    const int* __restrict__ rowptr, const int* __restrict__ csrsrc,
    float* __restrict__ hf, float* __restrict__ stats)
{
    const float2* rel2  = (const float2*)relf;
    const float2* root2 = (const float2*)rootf;
    float2* h2 = (float2*)hf;
    const int g  = threadIdx.x / 96;
    const int f2 = threadIdx.x % 96;
    float s0 = 0.f, s1 = 0.f, q0 = 0.f, q1 = 0.f;
    const int stride = gridDim.x * 2;
    for (int n = blockIdx.x * 2 + g; n < NN; n += stride) {
        const int st = __ldg(&rowptr[n]), en = __ldg(&rowptr[n + 1]);
        float2 acc = root2[(size_t)n * 96 + f2];
        int i = st;
        for (; i + 4 <= en; i += 4) {
            const int a0 = __ldg(&csrsrc[i]);
            const int a1 = __ldg(&csrsrc[i + 1]);
            const int a2 = __ldg(&csrsrc[i + 2]);
            const int a3 = __ldg(&csrsrc[i + 3]);
            const float2 v0 = rel2[(size_t)a0 * 96 + f2];
            const float2 v1 = rel2[(size_t)a1 * 96 + f2];
            const float2 v2 = rel2[(size_t)a2 * 96 + f2];
            const float2 v3 = rel2[(size_t)a3 * 96 + f2];
            acc.x += (v0.x + v1.x) + (v2.x + v3.x);
            acc.y += (v0.y + v1.y) + (v2.y + v3.y);
        }
        for (; i < en; i++) {
            const int a0 = __ldg(&csrsrc[i]);
            const float2 v0 = rel2[(size_t)a0 * 96 + f2];
            acc.x += v0.x; acc.y += v0.y;
        }
        h2[(size_t)n * 96 + f2] = acc;
        s0 += acc.x; q0 += acc.x * acc.x;
        s1 += acc.y; q1 += acc.y * acc.y;
    }
    const int f = f2 * 2;
    atomicAdd(&stats[f + 0], s0);
    atomicAdd(&stats[f + 1], s1);
    atomicAdd(&stats[HD + f + 0], q0);
    atomicAdd(&stats[HD + f + 1], q1);
}

__global__ void k_bn_finalize(const float* __restrict__ gamma, const float* __restrict__ beta,
                              int l, const float* __restrict__ stats, float* __restrict__ affine)
{
    int f = threadIdx.x;
    float mu = stats[f] / (float)NN;
    float var = stats[HD + f] / (float)NN - mu * mu;
    float a = gamma[l * HD + f] * rsqrtf(var + EPSV);
    affine[f] = a;
    affine[HD + f] = fmaf(-mu, a, beta[l * HD + f]);
}

__global__ void k_pool(const float* __restrict__ h, const int* __restrict__ gstart,
                       const float* __restrict__ affine, float* __restrict__ out)
{
    int g = blockIdx.x, f = threadIdx.x;
    int s = gstart[g], e = gstart[g + 1];
    float a = affine[f], bb = affine[HD + f];
    float acc = 0.f;
    for (int r = s; r < e; r++)
        acc += fmaxf(fmaf(h[(size_t)r * HD + f], a, bb), 0.f);
    int c = e - s;
    out[(size_t)g * HD + f] = acc / (float)(c > 0 ? c : 1);
}

// ---------------- head MLP (FFMA2 path, tiny) ---------------------------------
__device__ __forceinline__ void ffma2(ull& d, ull a, ull b) {
    asm("fma.rn.f32x2 %0, %1, %2, %0;" : "+l"(d) : "l"(a), "l"(b));
}
__device__ __forceinline__ ull pack2(float x) {
    ull r; asm("mov.b64 %0, {%1, %1};" : "=l"(r) : "f"(x)); return r;
}
__device__ __forceinline__ void unpack2(ull v, float& lo, float& hi) {
    asm("mov.b64 {%0, %1}, %2;" : "=f"(lo), "=f"(hi) : "l"(v));
}

__global__ __launch_bounds__(256) void k_gemm_head(
    const float* __restrict__ X, int M,
    const float* __restrict__ W1, const float* __restrict__ b1,
    float* __restrict__ O1, int mode)
{
    __shared__ float Xs[32][65];
    __shared__ float Ws1[32][64];
    const int tid = threadIdx.x;
    const int tx = tid & 15, ty = tid >> 4;
    const int row0 = blockIdx.x * 64, col0 = blockIdx.y * 64;
    ull acc1[4][2];
#pragma unroll
    for (int i = 0; i < 4; i++) { acc1[i][0] = 0ULL; acc1[i][1] = 0ULL; }
    for (int k0 = 0; k0 < HD; k0 += 32) {
#pragma unroll
        for (int i = 0; i < 8; i++) {
            int e = tid + i * 256, m = e >> 5, kk = e & 31;
            int r = row0 + m;
            float v = (r < M) ? X[(size_t)r * HD + (k0 + kk)] : 0.f;
            if (mode == 1) v = fmaxf(v, 0.f);
            Xs[kk][m] = v;
        }
#pragma unroll
        for (int i = 0; i < 8; i++) {
            int e = tid + i * 256, kk = e >> 6, n = e & 63;
            Ws1[kk][n] = W1[(size_t)(k0 + kk) * HD + col0 + n];
        }
        __syncthreads();
#pragma unroll
        for (int k = 0; k < 32; k++) {
            ull xp[4];
#pragma unroll
            for (int i = 0; i < 4; i++) xp[i] = pack2(Xs[k][ty * 4 + i]);
            const ull* w1 = reinterpret_cast<const ull*>(&Ws1[k][tx * 4]);
            ull w1a = w1[0], w1b = w1[1];
#pragma unroll
            for (int i = 0; i < 4; i++) { ffma2(acc1[i][0], xp[i], w1a); ffma2(acc1[i][1], xp[i], w1b); }
        }
        __syncthreads();
    }
    const int c = col0 + tx * 4;
    float bb0 = b1[c], bb1 = b1[c + 1], bb2 = b1[c + 2], bb3 = b1[c + 3];
#pragma unroll
    for (int i = 0; i < 4; i++) {
        int r = row0 + ty * 4 + i;
        if (r >= M) break;
        float4 o;
        unpack2(acc1[i][0], o.x, o.y);
        unpack2(acc1[i][1], o.z, o.w);
        o.x += bb0; o.y += bb1; o.z += bb2; o.w += bb3;
        *reinterpret_cast<float4*>(&O1[(size_t)r * HD + c]) = o;
    }
}

__global__ void k_out(const float* __restrict__ h2, const float* __restrict__ Wout,
                      const float* __restrict__ bout, float* __restrict__ out)
{
    int gid = blockIdx.x * blockDim.x + threadIdx.x;
    int lane = gid & 31, g = gid >> 5;
    if (g >= GG) return;
    float acc = 0.f;
#pragma unroll
    for (int k = lane; k < HD; k += 32)
        acc += h2[(size_t)g * HD + k] * Wout[k];
#pragma unroll
    for (int off = 16; off; off >>= 1)
        acc += __shfl_down_sync(0xffffffffu, acc, off);
    if (lane == 0) out[g] = acc + bout[0];
}

// ---------------- launch --------------------------------------------------------
extern "C" void kernel_launch(void* const* d_in, const int* in_sizes, int n_in,
                              void* d_out, int out_size)
{
    const float* x        = (const float*)d_in[0];
    const int*   edge_src = (const int*)d_in[1];
    const int*   edge_dst = (const int*)d_in[2];
    const int*   batch    = (const int*)d_in[3];
    const float* Wrel0    = (const float*)d_in[4];
    const float* brel0    = (const float*)d_in[5];
    const float* Wroot0   = (const float*)d_in[6];
    const float* Wrel     = (const float*)d_in[7];
    const float* brel     = (const float*)d_in[8];
    const float* Wroot    = (const float*)d_in[9];
    const float* gamma    = (const float*)d_in[10];
    const float* beta     = (const float*)d_in[11];
    const float* Wh1      = (const float*)d_in[12];
    const float* bh1      = (const float*)d_in[13];
    const float* Wh2      = (const float*)d_in[14];
    const float* bh2      = (const float*)d_in[15];
    const float* Wout     = (const float*)d_in[16];
    const float* bout     = (const float*)d_in[17];
    float* out = (float*)d_out;

    float *p_h, *p_rel, *p_agg, *p_stats, *p_affine, *p_pool, *p_t1, *p_t2;
    int *p_deg, *p_rowptr, *p_csrsrc, *p_bsum, *p_bsumx, *p_cnt, *p_gstart;
    __nv_bfloat16 *p_ahi, *p_alo, *p_x0hi, *p_x0lo, *p_wt0, *p_wtl;
    cudaGetSymbolAddress((void**)&p_h, g_h);
    cudaGetSymbolAddress((void**)&p_rel, g_rel);
    cudaGetSymbolAddress((void**)&p_agg, g_agg);
    cudaGetSymbolAddress((void**)&p_deg, g_deg);
    cudaGetSymbolAddress((void**)&p_rowptr, g_rowptr);
    cudaGetSymbolAddress((void**)&p_csrsrc, g_csrsrc);
    cudaGetSymbolAddress((void**)&p_bsum, g_bsum);
    cudaGetSymbolAddress((void**)&p_bsumx, g_bsumx);
    cudaGetSymbolAddress((void**)&p_cnt, g_cnt);
    cudaGetSymbolAddress((void**)&p_gstart, g_gstart);
    cudaGetSymbolAddress((void**)&p_stats, g_stats);
    cudaGetSymbolAddress((void**)&p_affine, g_affine);
    cudaGetSymbolAddress((void**)&p_pool, g_pool);
    cudaGetSymbolAddress((void**)&p_t1, g_t1);
    cudaGetSymbolAddress((void**)&p_t2, g_t2);
    cudaGetSymbolAddress((void**)&p_ahi, g_ahi);
    cudaGetSymbolAddress((void**)&p_alo, g_alo);
    cudaGetSymbolAddress((void**)&p_x0hi, g_x0hi);
    cudaGetSymbolAddress((void**)&p_x0lo, g_x0lo);
    cudaGetSymbolAddress((void**)&p_wt0, g_wt0);
    cudaGetSymbolAddress((void**)&p_wtl, g_wtl);

    const int smemS = 2 * 512 * 40 * 2;                 // 81920
    const int smemB = 20480 + 2 * 96 * (192 + 8) * 2;   // 97280
    cudaFuncSetAttribute(k_mma_s, cudaFuncAttributeMaxDynamicSharedMemorySize, smemS);
    cudaFuncSetAttribute(k_mma_b, cudaFuncAttributeMaxDynamicSharedMemorySize, smemB);

    const int nbScan = (NN + 1023) / 1024;

    // ---- prep (conv_x0 also zeros deg/cnt/stats); k_mma L0 at index 2 ----
    k_conv_x0<<<(NN * 8 + 255) / 256, 256>>>(x, p_x0hi, p_x0lo, p_deg, p_cnt, p_stats);
    k_prep_w<<<(3 * 2 * 192 * 192 + 255) / 256, 256>>>(Wrel0, Wroot0, Wrel, Wroot, p_wt0, p_wtl);
    k_mma_s<<<dim3((NN + 63) / 64, 2), 256, smemS>>>(p_x0hi, p_x0lo, 64, 32, NN,
                                                     p_wt0, p_wt0 + 2 * 192 * 64, 64,
                                                     brel0, p_rel, p_agg);

    // ---- CSR build ----
    k_count<<<(EE + 255) / 256, 256>>>(edge_dst, batch, p_deg, p_cnt);
    k_scan_block<<<nbScan, 1024>>>(p_deg, p_rowptr, p_bsum);
    k_scan_single<<<1, 1024>>>(p_bsum, p_bsumx, nbScan, 0);
    k_scan_fix<<<nbScan, 1024>>>(p_rowptr, p_bsumx, p_deg);
    k_fill<<<(EE + 255) / 256, 256>>>(edge_src, edge_dst, p_deg, p_csrsrc);

    // ---- GNN layers ----
    for (int l = 0; l < NL; l++) {
        if (l > 0) {
            const __nv_bfloat16* B0 = p_wtl + (size_t)(l - 1) * 4 * 192 * 192;
            const __nv_bfloat16* B1 = B0 + 2 * 192 * 192;
            k_mma_b<<<dim3(148, 4), 256, smemB>>>(p_ahi, p_alo, HD, HD, NN,
                                                  B0, B1, HD,
                                                  brel + (size_t)(l - 1) * HD, p_rel, p_agg);
        }
        k_aggstats<<<1184, 192>>>(p_rel, p_agg, p_rowptr, p_csrsrc, p_h,
                                  p_stats + (size_t)l * 2 * HD);
        if (l < NL - 1)
            k_act_conv<<<(NN * 48 + 255) / 256, 256>>>(p_h, p_stats + (size_t)l * 2 * HD,
                                                       gamma, beta, l, p_ahi, p_alo);
    }
    k_bn_finalize<<<1, HD>>>(gamma, beta, NL - 1,
                             p_stats + (size_t)(NL - 1) * 2 * HD, p_affine);

    // ---- pooling (applies last BN affine + relu) ----
    k_scan_single<<<1, 1024>>>(p_cnt, p_gstart, GG, 1);
    k_pool<<<GG, HD>>>(p_h, p_gstart, p_affine, p_pool);

    // ---- head MLP ----
    dim3 hgrid((GG + 63) / 64, HD / 64);
    k_gemm_head<<<hgrid, 256>>>(p_pool, GG, Wh1, bh1, p_t1, 0);
    k_gemm_head<<<hgrid, 256>>>(p_t1, GG, Wh2, bh2, p_t2, 1);
    k_out<<<(GG * 32 + 255) / 256, 256>>>(p_t2, Wout, bout, out);
}

// round 16
// speedup vs baseline: 1.0398x; 1.0398x over previous
#include <cuda_runtime.h>
#include <cuda_bf16.h>
#include <cstdint>

#define NN   100000
#define EE   400000
#define GG   2000
#define IND  32
#define HD   192
#define NL   4
#define EPSV 1e-5f

typedef unsigned long long ull;

// ---------------- persistent device scratch -------------------------------
__device__ float g_h[(size_t)NN * HD];
__device__ float g_rel[(size_t)NN * HD];
__device__ float g_agg[(size_t)NN * HD];
__device__ __nv_bfloat16 g_ahi[(size_t)NN * HD];
__device__ __nv_bfloat16 g_alo[(size_t)NN * HD];
__device__ __nv_bfloat16 g_x0hi[(size_t)NN * 64];
__device__ __nv_bfloat16 g_x0lo[(size_t)NN * 64];
__device__ __nv_bfloat16 g_wt0[2 * 2 * 192 * 64];        // [mat][split][192n * 64k]
__device__ __nv_bfloat16 g_wtl[3 * 2 * 2 * 192 * 192];   // [l][mat][split][192n * 192k]
__device__ int   g_deg[NN + 1];
__device__ int   g_rowptr[NN + 1];
__device__ int   g_csrsrc[EE];
__device__ int   g_bsum[128];
__device__ int   g_bsumx[128];
__device__ int   g_cnt[GG];
__device__ int   g_gstart[GG + 1];
__device__ float g_stats[NL * 2 * HD];
__device__ float g_affine[2 * HD];
__device__ float g_pool[(size_t)GG * HD];
__device__ float g_t1[(size_t)GG * HD];
__device__ float g_t2[(size_t)GG * HD];

// ---------------- PTX helpers ----------------------------------------------
__device__ __forceinline__ uint32_t smem_u32(const void* p) {
    uint32_t a;
    asm("{ .reg .u64 t; cvta.to.shared.u64 t, %1; cvt.u32.u64 %0, t; }"
        : "=r"(a) : "l"(p));
    return a;
}

__device__ __forceinline__ void mma_bf16(float* d, const uint32_t* a, const uint32_t* b) {
    asm volatile(
        "mma.sync.aligned.m16n8k16.row.col.f32.bf16.bf16.f32 "
        "{%0,%1,%2,%3}, {%4,%5,%6,%7}, {%8,%9}, {%0,%1,%2,%3};"
        : "+f"(d[0]), "+f"(d[1]), "+f"(d[2]), "+f"(d[3])
        : "r"(a[0]), "r"(a[1]), "r"(a[2]), "r"(a[3]), "r"(b[0]), "r"(b[1]));
}

#define LDSM4(r, addr) \
    asm volatile("ldmatrix.sync.aligned.m8n8.x4.shared.b16 {%0,%1,%2,%3}, [%4];" \
                 : "=r"((r)[0]), "=r"((r)[1]), "=r"((r)[2]), "=r"((r)[3]) : "r"(addr))

__device__ __forceinline__ void cpa16(uint32_t dst, const void* src, int srcBytes) {
    asm volatile("cp.async.cg.shared.global [%0], [%1], 16, %2;"
                 :: "r"(dst), "l"(src), "r"(srcBytes) : "memory");
}
#define CP_COMMIT() asm volatile("cp.async.commit_group;" ::: "memory")
#define CP_WAIT(n)  asm volatile("cp.async.wait_group %0;" :: "n"(n) : "memory")

// ======= GEMM variant 1: streaming, M64xN192, for L0 (K=32) ================
__global__ __launch_bounds__(256, 2) void k_mma_s(
    const __nv_bfloat16* __restrict__ Xhi, const __nv_bfloat16* __restrict__ Xlo,
    int ldA, int K, int M,
    const __nv_bfloat16* __restrict__ B0, const __nv_bfloat16* __restrict__ B1,
    int ldB, const float* __restrict__ bias,
    float* __restrict__ O1, float* __restrict__ O2)
{
    extern __shared__ __nv_bfloat16 sm[];
    const int chunk = (K < 32) ? K : 32;
    const int S = chunk + 8;
    const int tid = threadIdx.x, lane = tid & 31, wid = tid >> 5;
    const int warpM = wid & 1, warpN = wid >> 1;
    const int row0 = blockIdx.x * 64;
    const int mat = blockIdx.y;
    const __nv_bfloat16* Bbase = mat ? B1 : B0;
    const size_t splitOffB = (size_t)192 * ldB;

    const uint32_t sb = smem_u32(sm);
    const uint32_t offAlo   = 64 * S * 2;
    const uint32_t offBh    = 128 * S * 2;
    const uint32_t offBlo   = 192 * S * 2;
    const uint32_t stageSz  = (128 + 384) * S * 2;

    float d[2][6][4];
#pragma unroll
    for (int a = 0; a < 2; a++)
#pragma unroll
        for (int b = 0; b < 6; b++)
#pragma unroll
            for (int c = 0; c < 4; c++) d[a][b][c] = 0.f;

    const uint32_t aAddr = sb +
        (((warpM * 32 + (lane & 15)) * S + ((lane >> 4) * 8)) * 2);
    const uint32_t bAddr = sb + offBh +
        (((warpN * 48 + (lane & 7) + ((lane >> 4) << 3)) * S + (((lane >> 3) & 1) * 8)) * 2);
    const uint32_t step16 = 16 * S * 2;

    const int cv = chunk >> 3;
    const int nChunks = K / chunk;

    auto load_chunk = [&](int c, int stage) {
        const uint32_t st = sb + stage * stageSz;
        const int kc = c * chunk;
        for (int idx = tid; idx < 64 * cv; idx += 256) {
            const int rr = idx / cv, kv = idx % cv;
            const int row = row0 + rr;
            const int ok = (row < M) ? 16 : 0;
            const size_t so = (size_t)(ok ? row : 0) * ldA + kc + kv * 8;
            const uint32_t doff = (rr * S + kv * 8) * 2;
            cpa16(st + doff, Xhi + so, ok);
            cpa16(st + offAlo + doff, Xlo + so, ok);
        }
        for (int idx = tid; idx < 192 * cv; idx += 256) {
            const int nn = idx / cv, kv = idx % cv;
            const __nv_bfloat16* src = Bbase + (size_t)nn * ldB + kc + kv * 8;
            const uint32_t doff = (nn * S + kv * 8) * 2;
            cpa16(st + offBh + doff, src, 16);
            cpa16(st + offBh + offBlo + doff, src + splitOffB, 16);
        }
        CP_COMMIT();
    };

    load_chunk(0, 0);

    for (int c = 0; c < nChunks; c++) {
        const int stage = c & 1;
        if (c + 1 < nChunks) { load_chunk(c + 1, stage ^ 1); CP_WAIT(1); }
        else                 { CP_WAIT(0); }
        __syncthreads();

        const uint32_t so = stage * stageSz;
        const int nk = chunk >> 4;
        for (int ks = 0; ks < nk; ks++) {
            const uint32_t kb = (uint32_t)ks * 32;
            uint32_t ah0[4], al0[4], ah1[4], al1[4];
            LDSM4(ah0, aAddr + so + kb);
            LDSM4(al0, aAddr + so + kb + offAlo);
            LDSM4(ah1, aAddr + so + kb + step16);
            LDSM4(al1, aAddr + so + kb + step16 + offAlo);
#pragma unroll
            for (int p = 0; p < 3; p++) {
                uint32_t bh4[4], bl4[4];
                LDSM4(bh4, bAddr + so + kb + p * step16);
                LDSM4(bl4, bAddr + so + kb + p * step16 + offBlo);
#pragma unroll
                for (int hh = 0; hh < 2; hh++) {
                    const int nj = p * 2 + hh;
                    const uint32_t* b_h = &bh4[hh * 2];
                    const uint32_t* b_l = &bl4[hh * 2];
                    mma_bf16(d[0][nj], ah0, b_h);
                    mma_bf16(d[0][nj], ah0, b_l);
                    mma_bf16(d[0][nj], al0, b_h);
                    mma_bf16(d[1][nj], ah1, b_h);
                    mma_bf16(d[1][nj], ah1, b_l);
                    mma_bf16(d[1][nj], al1, b_h);
                }
            }
        }
        __syncthreads();
    }

    const int r = lane >> 2, cq = lane & 3;
    float* O = mat ? O2 : O1;
#pragma unroll
    for (int nj = 0; nj < 6; nj++) {
        const int col = warpN * 48 + nj * 8 + cq * 2;
        float b0 = 0.f, b1v = 0.f;
        if (mat == 0 && bias) { b0 = bias[col]; b1v = bias[col + 1]; }
#pragma unroll
        for (int mi = 0; mi < 2; mi++) {
            const int rr = row0 + warpM * 32 + mi * 16 + r;
            if (rr < M) {
                float2 v = make_float2(d[mi][nj][0] + b0, d[mi][nj][1] + b1v);
                *(float2*)(&O[(size_t)rr * HD + col]) = v;
            }
            if (rr + 8 < M) {
                float2 v = make_float2(d[mi][nj][2] + b0, d[mi][nj][3] + b1v);
                *(float2*)(&O[(size_t)(rr + 8) * HD + col]) = v;
            }
        }
    }
}

// ======= GEMM variant 2: B-resident (R14 exact), for K=192 layers ===========
__global__ __launch_bounds__(256, 2) void k_mma_b(
    const __nv_bfloat16* __restrict__ Xhi, const __nv_bfloat16* __restrict__ Xlo,
    int ldA, int K, int M,
    const __nv_bfloat16* __restrict__ B0, const __nv_bfloat16* __restrict__ B1,
    int ldB, const float* __restrict__ bias,
    float* __restrict__ O1, float* __restrict__ O2)
{
    extern __shared__ __nv_bfloat16 sm[];
    const int chunk = (K < 32) ? K : 32;
    const int S = chunk + 8;
    const int SB = K + 8;
    const int tid = threadIdx.x, lane = tid & 31, wid = tid >> 5;
    const int warpM = wid & 3, warpN = wid >> 2;
    const int mat = blockIdx.y >> 1;
    const int ncol0 = (blockIdx.y & 1) * 96;
    const __nv_bfloat16* Bbase = mat ? B1 : B0;
    const size_t splitOffB = (size_t)192 * ldB;

    const uint32_t sb = smem_u32(sm);
    const uint32_t offAlo   = 64 * S * 2;
    const uint32_t stageSz  = 128 * S * 2;
    const uint32_t offB     = 2 * stageSz;
    const uint32_t offBlo   = (uint32_t)(96 * SB * 2);

    // ---- B resident load (once) ----
    const int KV = K >> 3;
    for (int idx = tid; idx < 96 * KV; idx += 256) {
        const int nn = idx / KV, kv = idx % KV;
        const __nv_bfloat16* src = Bbase + (size_t)(ncol0 + nn) * ldB + kv * 8;
        const uint32_t doff = (uint32_t)((nn * SB + kv * 8) * 2);
        cpa16(sb + offB + doff, src, 16);
        cpa16(sb + offB + offBlo + doff, src + splitOffB, 16);
    }
    CP_COMMIT();

    const uint32_t aAddr = sb +
        (((warpM * 16 + (lane & 15)) * S + ((lane >> 4) * 8)) * 2);
    const uint32_t bAddr = sb + offB +
        (uint32_t)((((warpN * 48 + (lane & 7) + ((lane >> 4) << 3)) * SB) +
                    (((lane >> 3) & 1) * 8)) * 2);
    const uint32_t bStep16 = (uint32_t)(16 * SB * 2);

    const int cv = chunk >> 3;
    const int nChunks = K / chunk;
    const int nTiles = (M + 63) >> 6;

    const int r = lane >> 2, cq = lane & 3;
    float* O = mat ? O2 : O1;

    auto loadA = [&](int row0, int c, int stage) {
        const uint32_t st = sb + stage * stageSz;
        const int kc = c * chunk;
        for (int idx = tid; idx < 64 * cv; idx += 256) {
            const int rr = idx / cv, kv = idx % cv;
            const int row = row0 + rr;
            const int ok = (row < M) ? 16 : 0;
            const size_t so = (size_t)(ok ? row : 0) * ldA + kc + kv * 8;
            const uint32_t doff = (rr * S + kv * 8) * 2;
            cpa16(st + doff, Xhi + so, ok);
            cpa16(st + offAlo + doff, Xlo + so, ok);
        }
        CP_COMMIT();
    };

    for (int mt = blockIdx.x; mt < nTiles; mt += gridDim.x) {
        const int row0 = mt * 64;

        float d[6][4];
#pragma unroll
        for (int b = 0; b < 6; b++)
#pragma unroll
            for (int c = 0; c < 4; c++) d[b][c] = 0.f;

        loadA(row0, 0, 0);

        for (int c = 0; c < nChunks; c++) {
            const int stage = c & 1;
            if (c + 1 < nChunks) { loadA(row0, c + 1, stage ^ 1); CP_WAIT(1); }
            else                 { CP_WAIT(0); }
            __syncthreads();

            const uint32_t so = stage * stageSz;
            const int nk = chunk >> 4;
            for (int ks = 0; ks < nk; ks++) {
                const uint32_t kbA = (uint32_t)ks * 32;
                const uint32_t kcol = (uint32_t)((c * chunk + ks * 16) * 2);
                uint32_t ah[4], al[4];
                LDSM4(ah, aAddr + so + kbA);
                LDSM4(al, aAddr + so + kbA + offAlo);
#pragma unroll
                for (int p = 0; p < 3; p++) {
                    uint32_t bh4[4], bl4[4];
                    LDSM4(bh4, bAddr + kcol + p * bStep16);
                    LDSM4(bl4, bAddr + kcol + p * bStep16 + offBlo);
#pragma unroll
                    for (int hh = 0; hh < 2; hh++) {
                        const int nj = p * 2 + hh;
                        const uint32_t* b_h = &bh4[hh * 2];
                        const uint32_t* b_l = &bl4[hh * 2];
                        mma_bf16(d[nj], ah, b_h);
                        mma_bf16(d[nj], ah, b_l);
                        mma_bf16(d[nj], al, b_h);
                    }
                }
            }
            __syncthreads();
        }

#pragma unroll
        for (int nj = 0; nj < 6; nj++) {
            const int col = ncol0 + warpN * 48 + nj * 8 + cq * 2;
            float b0 = 0.f, b1v = 0.f;
            if (mat == 0 && bias) { b0 = bias[col]; b1v = bias[col + 1]; }
            const int rr = row0 + warpM * 16 + r;
            if (rr < M) {
                float2 v = make_float2(d[nj][0] + b0, d[nj][1] + b1v);
                *(float2*)(&O[(size_t)rr * HD + col]) = v;
            }
            if (rr + 8 < M) {
                float2 v = make_float2(d[nj][2] + b0, d[nj][3] + b1v);
                *(float2*)(&O[(size_t)(rr + 8) * HD + col]) = v;
            }
        }
    }
}

// ---------------- weight / activation prep ----------------------------------
__device__ __forceinline__ void split_bf16(float v, __nv_bfloat16& h, __nv_bfloat16& l) {
    h = __float2bfloat16(v);
    l = __float2bfloat16(v - __bfloat162float(h));
}
__device__ __forceinline__ uint32_t pk_bf16(__nv_bfloat16 a, __nv_bfloat16 b) {
    __nv_bfloat162 t(a, b);
    return *reinterpret_cast<uint32_t*>(&t);
}

__global__ void k_prep_w(const float* __restrict__ Wrel0, const float* __restrict__ Wroot0,
                         const float* __restrict__ Wrel, const float* __restrict__ Wroot,
                         __nv_bfloat16* wt0, __nv_bfloat16* wtl)
{
    int i = blockIdx.x * blockDim.x + threadIdx.x;
    if (i < 2 * 192 * 64) {
        int mat = i / (192 * 64), r = i % (192 * 64);
        int n = r / 64, k = r % 64;
        const float* W = mat ? Wroot0 : Wrel0;
        float v = (k < IND) ? W[k * HD + n] : 0.f;
        __nv_bfloat16 h, l; split_bf16(v, h, l);
        wt0[mat * (2 * 192 * 64) + r] = h;
        wt0[mat * (2 * 192 * 64) + 192 * 64 + r] = l;
    }
    if (i < 3 * 2 * 192 * 192) {
        int ly = i / (2 * 192 * 192), r1 = i % (2 * 192 * 192);
        int mat = r1 / (192 * 192), r = r1 % (192 * 192);
        int n = r / 192, k = r % 192;
        const float* W = (mat ? Wroot : Wrel) + (size_t)ly * HD * HD;
        float v = W[k * HD + n];
        __nv_bfloat16 h, l; split_bf16(v, h, l);
        wtl[(size_t)((ly * 2 + mat) * 2 + 0) * (192 * 192) + r] = h;
        wtl[(size_t)((ly * 2 + mat) * 2 + 1) * (192 * 192) + r] = l;
    }
}

// input split + zero deg/cnt/stats (folded zero_csr)
__global__ void k_conv_x0(const float* __restrict__ x,
                          __nv_bfloat16* __restrict__ xhi, __nv_bfloat16* __restrict__ xlo,
                          int* deg, int* cnt, float* stats)
{
    size_t i = (size_t)blockIdx.x * blockDim.x + threadIdx.x;
    if (i < NN) deg[i] = 0;
    if (i < GG) cnt[i] = 0;
    if (i < NL * 2 * HD) stats[i] = 0.f;
    if (i >= (size_t)NN * 8) return;
    const int row = (int)(i >> 3), oct = (int)(i & 7);
    __nv_bfloat16 h[8], l[8];
    if (oct < 4) {
        const float4 v0 = *(const float4*)(x + (size_t)row * IND + oct * 8);
        const float4 v1 = *(const float4*)(x + (size_t)row * IND + oct * 8 + 4);
        split_bf16(v0.x, h[0], l[0]); split_bf16(v0.y, h[1], l[1]);
        split_bf16(v0.z, h[2], l[2]); split_bf16(v0.w, h[3], l[3]);
        split_bf16(v1.x, h[4], l[4]); split_bf16(v1.y, h[5], l[5]);
        split_bf16(v1.z, h[6], l[6]); split_bf16(v1.w, h[7], l[7]);
    } else {
#pragma unroll
        for (int k = 0; k < 8; k++) { h[k] = __float2bfloat16(0.f); l[k] = h[k]; }
    }
    uint4 hv = make_uint4(pk_bf16(h[0], h[1]), pk_bf16(h[2], h[3]),
                          pk_bf16(h[4], h[5]), pk_bf16(h[6], h[7]));
    uint4 lv = make_uint4(pk_bf16(l[0], l[1]), pk_bf16(l[2], l[3]),
                          pk_bf16(l[4], l[5]), pk_bf16(l[6], l[7]));
    *(uint4*)(xhi + (size_t)row * 64 + oct * 8) = hv;
    *(uint4*)(xlo + (size_t)row * 64 + oct * 8) = lv;
}

// relu(a*h + b) -> bf16 hi/lo (R14 exact: affine precomputed)
__global__ void k_act_conv(const float* __restrict__ h, const float* __restrict__ affine,
                           __nv_bfloat16* __restrict__ ahi, __nv_bfloat16* __restrict__ alo)
{
    size_t i = (size_t)blockIdx.x * blockDim.x + threadIdx.x;
    if (i >= (size_t)NN * 48) return;
    const int f4 = (int)(i % 48);
    const float4 v  = *(const float4*)(h + i * 4);
    const float4 a4 = *(const float4*)(affine + f4 * 4);
    const float4 b4 = *(const float4*)(affine + HD + f4 * 4);
    float x0 = fmaxf(fmaf(v.x, a4.x, b4.x), 0.f);
    float x1 = fmaxf(fmaf(v.y, a4.y, b4.y), 0.f);
    float x2 = fmaxf(fmaf(v.z, a4.z, b4.z), 0.f);
    float x3 = fmaxf(fmaf(v.w, a4.w, b4.w), 0.f);
    __nv_bfloat16 h0, h1, h2, h3, l0, l1, l2, l3;
    split_bf16(x0, h0, l0); split_bf16(x1, h1, l1);
    split_bf16(x2, h2, l2); split_bf16(x3, h3, l3);
    *(uint2*)(ahi + i * 4) = make_uint2(pk_bf16(h0, h1), pk_bf16(h2, h3));
    *(uint2*)(alo + i * 4) = make_uint2(pk_bf16(l0, l1), pk_bf16(l2, l3));
}

// ---------------- CSR build ---------------------------------------------------
__global__ void k_count(const int* __restrict__ dst, const int* __restrict__ batch,
                        int* deg, int* cnt) {
    int i = blockIdx.x * blockDim.x + threadIdx.x;
    if (i < EE) atomicAdd(&deg[dst[i]], 1);
    if (i < NN) atomicAdd(&cnt[batch[i]], 1);
}
__global__ void k_scan_block(const int* __restrict__ in, int* rowptr, int* bsum) {
    __shared__ int s[1024];
    int t = threadIdx.x;
    int i = blockIdx.x * 1024 + t;
    int v = (i < NN) ? in[i] : 0;
    s[t] = v;
    __syncthreads();
#pragma unroll
    for (int off = 1; off < 1024; off <<= 1) {
        int add = (t >= off) ? s[t - off] : 0;
        __syncthreads();
        s[t] += add;
        __syncthreads();
    }
    if (i < NN) rowptr[i + 1] = s[t];
    if (t == 1023) bsum[blockIdx.x] = s[1023];
}
__global__ void k_scan_single(const int* __restrict__ in, int* out, int n, int writeTotal) {
    __shared__ int s[1024];
    __shared__ int carry;
    int t = threadIdx.x;
    if (t == 0) carry = 0;
    __syncthreads();
    for (int c0 = 0; c0 < n; c0 += 1024) {
        int v = (c0 + t < n) ? in[c0 + t] : 0;
        s[t] = v;
        __syncthreads();
#pragma unroll
        for (int off = 1; off < 1024; off <<= 1) {
            int add = (t >= off) ? s[t - off] : 0;
            __syncthreads();
            s[t] += add;
            __syncthreads();
        }
        if (c0 + t < n) out[c0 + t] = carry + s[t] - v;
        __syncthreads();
        if (t == 1023) carry += s[1023];
        __syncthreads();
    }
    if (t == 0 && writeTotal) out[n] = carry;
}
// fix rowptr (add block prefix) AND write the fill cursor (folded copy_cursor)
__global__ void k_scan_fix(int* rowptr, const int* __restrict__ bsumx, int* cursor) {
    int i = blockIdx.x * 1024 + threadIdx.x;
    if (i < NN) {
        const int v = rowptr[i + 1] + bsumx[blockIdx.x];
        rowptr[i + 1] = v;
        if (i + 1 < NN) cursor[i + 1] = v;
    }
    if (i == 0) { rowptr[0] = 0; cursor[0] = 0; }
}
__global__ void k_fill(const int* __restrict__ src, const int* __restrict__ dst,
                       int* cursor, int* csrsrc) {
    int i = blockIdx.x * blockDim.x + threadIdx.x;
    if (i < EE) {
        int slot = atomicAdd(&cursor[dst[i]], 1);
        csrsrc[slot] = src[i];
    }
}

// ---------------- fused aggregate + BN stats (float2, 96-thr warp-aligned) ---
__global__ __launch_bounds__(192) void k_aggstats(
    const float* __restrict__ relf, const float* __restrict__ rootf,
    const int* __restrict__ rowptr, const int* __restrict__ csrsrc,
    float* __restrict__ hf, float* __restrict__ stats)
{
    const float2* rel2  = (const float2*)relf;
    const float2* root2 = (const float2*)rootf;
    float2* h2 = (float2*)hf;
    const int g  = threadIdx.x / 96;
    const int f2 = threadIdx.x % 96;
    float s0 = 0.f, s1 = 0.f, q0 = 0.f, q1 = 0.f;
    const int stride = gridDim.x * 2;
    for (int n = blockIdx.x * 2 + g; n < NN; n += stride) {
        const int st = __ldg(&rowptr[n]), en = __ldg(&rowptr[n + 1]);
        float2 acc = root2[(size_t)n * 96 + f2];
        int i = st;
        for (; i + 4 <= en; i += 4) {
            const int a0 = __ldg(&csrsrc[i]);
            const int a1 = __ldg(&csrsrc[i + 1]);
            const int a2 = __ldg(&csrsrc[i + 2]);
            const int a3 = __ldg(&csrsrc[i + 3]);
            const float2 v0 = rel2[(size_t)a0 * 96 + f2];
            const float2 v1 = rel2[(size_t)a1 * 96 + f2];
            const float2 v2 = rel2[(size_t)a2 * 96 + f2];
            const float2 v3 = rel2[(size_t)a3 * 96 + f2];
            acc.x += (v0.x + v1.x) + (v2.x + v3.x);
            acc.y += (v0.y + v1.y) + (v2.y + v3.y);
        }
        for (; i < en; i++) {
            const int a0 = __ldg(&csrsrc[i]);
            const float2 v0 = rel2[(size_t)a0 * 96 + f2];
            acc.x += v0.x; acc.y += v0.y;
        }
        h2[(size_t)n * 96 + f2] = acc;
        s0 += acc.x; q0 += acc.x * acc.x;
        s1 += acc.y; q1 += acc.y * acc.y;
    }
    const int f = f2 * 2;
    atomicAdd(&stats[f + 0], s0);
    atomicAdd(&stats[f + 1], s1);
    atomicAdd(&stats[HD + f + 0], q0);
    atomicAdd(&stats[HD + f + 1], q1);
}

__global__ void k_bn_finalize(const float* __restrict__ gamma, const float* __restrict__ beta,
                              int l, const float* __restrict__ stats, float* __restrict__ affine)
{
    int f = threadIdx.x;
    float mu = stats[f] / (float)NN;
    float var = stats[HD + f] / (float)NN - mu * mu;
    float a = gamma[l * HD + f] * rsqrtf(var + EPSV);
    affine[f] = a;
    affine[HD + f] = fmaf(-mu, a, beta[l * HD + f]);
}

__global__ void k_pool(const float* __restrict__ h, const int* __restrict__ gstart,
                       const float* __restrict__ affine, float* __restrict__ out)
{
    int g = blockIdx.x, f = threadIdx.x;
    int s = gstart[g], e = gstart[g + 1];
    float a = affine[f], bb = affine[HD + f];
    float acc = 0.f;
    for (int r = s; r < e; r++)
        acc += fmaxf(fmaf(h[(size_t)r * HD + f], a, bb), 0.f);
    int c = e - s;
    out[(size_t)g * HD + f] = acc / (float)(c > 0 ? c : 1);
}

// ---------------- head MLP (FFMA2 path, tiny) ---------------------------------
__device__ __forceinline__ void ffma2(ull& d, ull a, ull b) {
    asm("fma.rn.f32x2 %0, %1, %2, %0;" : "+l"(d) : "l"(a), "l"(b));
}
__device__ __forceinline__ ull pack2(float x) {
    ull r; asm("mov.b64 %0, {%1, %1};" : "=l"(r) : "f"(x)); return r;
}
__device__ __forceinline__ void unpack2(ull v, float& lo, float& hi) {
    asm("mov.b64 {%0, %1}, %2;" : "=f"(lo), "=f"(hi) : "l"(v));
}

__global__ __launch_bounds__(256) void k_gemm_head(
    const float* __restrict__ X, int M,
    const float* __restrict__ W1, const float* __restrict__ b1,
    float* __restrict__ O1, int mode)
{
    __shared__ float Xs[32][65];
    __shared__ float Ws1[32][64];
    const int tid = threadIdx.x;
    const int tx = tid & 15, ty = tid >> 4;
    const int row0 = blockIdx.x * 64, col0 = blockIdx.y * 64;
    ull acc1[4][2];
#pragma unroll
    for (int i = 0; i < 4; i++) { acc1[i][0] = 0ULL; acc1[i][1] = 0ULL; }
    for (int k0 = 0; k0 < HD; k0 += 32) {
#pragma unroll
        for (int i = 0; i < 8; i++) {
            int e = tid + i * 256, m = e >> 5, kk = e & 31;
            int r = row0 + m;
            float v = (r < M) ? X[(size_t)r * HD + (k0 + kk)] : 0.f;
            if (mode == 1) v = fmaxf(v, 0.f);
            Xs[kk][m] = v;
        }
#pragma unroll
        for (int i = 0; i < 8; i++) {
            int e = tid + i * 256, kk = e >> 6, n = e & 63;
            Ws1[kk][n] = W1[(size_t)(k0 + kk) * HD + col0 + n];
        }
        __syncthreads();
#pragma unroll
        for (int k = 0; k < 32; k++) {
            ull xp[4];
#pragma unroll
            for (int i = 0; i < 4; i++) xp[i] = pack2(Xs[k][ty * 4 + i]);
            const ull* w1 = reinterpret_cast<const ull*>(&Ws1[k][tx * 4]);
            ull w1a = w1[0], w1b = w1[1];
#pragma unroll
            for (int i = 0; i < 4; i++) { ffma2(acc1[i][0], xp[i], w1a); ffma2(acc1[i][1], xp[i], w1b); }
        }
        __syncthreads();
    }
    const int c = col0 + tx * 4;
    float bb0 = b1[c], bb1 = b1[c + 1], bb2 = b1[c + 2], bb3 = b1[c + 3];
#pragma unroll
    for (int i = 0; i < 4; i++) {
        int r = row0 + ty * 4 + i;
        if (r >= M) break;
        float4 o;
        unpack2(acc1[i][0], o.x, o.y);
        unpack2(acc1[i][1], o.z, o.w);
        o.x += bb0; o.y += bb1; o.z += bb2; o.w += bb3;
        *reinterpret_cast<float4*>(&O1[(size_t)r * HD + c]) = o;
    }
}

__global__ void k_out(const float* __restrict__ h2, const float* __restrict__ Wout,
                      const float* __restrict__ bout, float* __restrict__ out)
{
    int gid = blockIdx.x * blockDim.x + threadIdx.x;
    int lane = gid & 31, g = gid >> 5;
    if (g >= GG) return;
    float acc = 0.f;
#pragma unroll
    for (int k = lane; k < HD; k += 32)
        acc += h2[(size_t)g * HD + k] * Wout[k];
#pragma unroll
    for (int off = 16; off; off >>= 1)
        acc += __shfl_down_sync(0xffffffffu, acc, off);
    if (lane == 0) out[g] = acc + bout[0];
}

// ---------------- launch --------------------------------------------------------
extern "C" void kernel_launch(void* const* d_in, const int* in_sizes, int n_in,
                              void* d_out, int out_size)
{
    const float* x        = (const float*)d_in[0];
    const int*   edge_src = (const int*)d_in[1];
    const int*   edge_dst = (const int*)d_in[2];
    const int*   batch    = (const int*)d_in[3];
    const float* Wrel0    = (const float*)d_in[4];
    const float* brel0    = (const float*)d_in[5];
    const float* Wroot0   = (const float*)d_in[6];
    const float* Wrel     = (const float*)d_in[7];
    const float* brel     = (const float*)d_in[8];
    const float* Wroot    = (const float*)d_in[9];
    const float* gamma    = (const float*)d_in[10];
    const float* beta     = (const float*)d_in[11];
    const float* Wh1      = (const float*)d_in[12];
    const float* bh1      = (const float*)d_in[13];
    const float* Wh2      = (const float*)d_in[14];
    const float* bh2      = (const float*)d_in[15];
    const float* Wout     = (const float*)d_in[16];
    const float* bout     = (const float*)d_in[17];
    float* out = (float*)d_out;

    float *p_h, *p_rel, *p_agg, *p_stats, *p_affine, *p_pool, *p_t1, *p_t2;
    int *p_deg, *p_rowptr, *p_csrsrc, *p_bsum, *p_bsumx, *p_cnt, *p_gstart;
    __nv_bfloat16 *p_ahi, *p_alo, *p_x0hi, *p_x0lo, *p_wt0, *p_wtl;
    cudaGetSymbolAddress((void**)&p_h, g_h);
    cudaGetSymbolAddress((void**)&p_rel, g_rel);
    cudaGetSymbolAddress((void**)&p_agg, g_agg);
    cudaGetSymbolAddress((void**)&p_deg, g_deg);
    cudaGetSymbolAddress((void**)&p_rowptr, g_rowptr);
    cudaGetSymbolAddress((void**)&p_csrsrc, g_csrsrc);
    cudaGetSymbolAddress((void**)&p_bsum, g_bsum);
    cudaGetSymbolAddress((void**)&p_bsumx, g_bsumx);
    cudaGetSymbolAddress((void**)&p_cnt, g_cnt);
    cudaGetSymbolAddress((void**)&p_gstart, g_gstart);
    cudaGetSymbolAddress((void**)&p_stats, g_stats);
    cudaGetSymbolAddress((void**)&p_affine, g_affine);
    cudaGetSymbolAddress((void**)&p_pool, g_pool);
    cudaGetSymbolAddress((void**)&p_t1, g_t1);
    cudaGetSymbolAddress((void**)&p_t2, g_t2);
    cudaGetSymbolAddress((void**)&p_ahi, g_ahi);
    cudaGetSymbolAddress((void**)&p_alo, g_alo);
    cudaGetSymbolAddress((void**)&p_x0hi, g_x0hi);
    cudaGetSymbolAddress((void**)&p_x0lo, g_x0lo);
    cudaGetSymbolAddress((void**)&p_wt0, g_wt0);
    cudaGetSymbolAddress((void**)&p_wtl, g_wtl);

    const int smemS = 2 * 512 * 40 * 2;                 // 81920
    const int smemB = 20480 + 2 * 96 * (192 + 8) * 2;   // 97280
    cudaFuncSetAttribute(k_mma_s, cudaFuncAttributeMaxDynamicSharedMemorySize, smemS);
    cudaFuncSetAttribute(k_mma_b, cudaFuncAttributeMaxDynamicSharedMemorySize, smemB);

    const int nbScan = (NN + 1023) / 1024;

    // ---- prep (conv_x0 also zeros deg/cnt/stats) ----
    k_conv_x0<<<(NN * 8 + 255) / 256, 256>>>(x, p_x0hi, p_x0lo, p_deg, p_cnt, p_stats);
    k_prep_w<<<(3 * 2 * 192 * 192 + 255) / 256, 256>>>(Wrel0, Wroot0, Wrel, Wroot, p_wt0, p_wtl);
    k_mma_s<<<dim3((NN + 63) / 64, 2), 256, smemS>>>(p_x0hi, p_x0lo, 64, 32, NN,
                                                     p_wt0, p_wt0 + 2 * 192 * 64, 64,
                                                     brel0, p_rel, p_agg);

    // ---- CSR build ----
    k_count<<<(EE + 255) / 256, 256>>>(edge_dst, batch, p_deg, p_cnt);
    k_scan_block<<<nbScan, 1024>>>(p_deg, p_rowptr, p_bsum);
    k_scan_single<<<1, 1024>>>(p_bsum, p_bsumx, nbScan, 0);
    k_scan_fix<<<nbScan, 1024>>>(p_rowptr, p_bsumx, p_deg);
    k_fill<<<(EE + 255) / 256, 256>>>(edge_src, edge_dst, p_deg, p_csrsrc);

    // ---- GNN layers ----
    for (int l = 0; l < NL; l++) {
        if (l > 0) {
            const __nv_bfloat16* B0 = p_wtl + (size_t)(l - 1) * 4 * 192 * 192;
            const __nv_bfloat16* B1 = B0 + 2 * 192 * 192;
            k_mma_b<<<dim3(148, 4), 256, smemB>>>(p_ahi, p_alo, HD, HD, NN,
                                                  B0, B1, HD,
                                                  brel + (size_t)(l - 1) * HD, p_rel, p_agg);
        }
        k_aggstats<<<1184, 192>>>(p_rel, p_agg, p_rowptr, p_csrsrc, p_h,
                                  p_stats + (size_t)l * 2 * HD);
        k_bn_finalize<<<1, HD>>>(gamma, beta, l, p_stats + (size_t)l * 2 * HD, p_affine);
        if (l < NL - 1)
            k_act_conv<<<(NN * 48 + 255) / 256, 256>>>(p_h, p_affine, p_ahi, p_alo);
    }

    // ---- pooling (applies last BN affine + relu) ----
    k_scan_single<<<1, 1024>>>(p_cnt, p_gstart, GG, 1);
    k_pool<<<GG, HD>>>(p_h, p_gstart, p_affine, p_pool);

    // ---- head MLP ----
    dim3 hgrid((GG + 63) / 64, HD / 64);
    k_gemm_head<<<hgrid, 256>>>(p_pool, GG, Wh1, bh1, p_t1, 0);
    k_gemm_head<<<hgrid, 256>>>(p_t1, GG, Wh2, bh2, p_t2, 1);
    k_out<<<(GG * 32 + 255) / 256, 256>>>(p_t2, Wout, bout, out);
}

// round 17
// speedup vs baseline: 1.0499x; 1.0097x over previous
#include <cuda_runtime.h>
#include <cuda_bf16.h>
#include <cstdint>

#define NN   100000
#define EE   400000
#define GG   2000
#define IND  32
#define HD   192
#define NL   4
#define EPSV 1e-5f

typedef unsigned long long ull;

// ---------------- persistent device scratch -------------------------------
__device__ float g_h[(size_t)NN * HD];
__device__ float g_rel[(size_t)NN * HD];
__device__ float g_agg[(size_t)NN * HD];
__device__ __nv_bfloat16 g_ahi[(size_t)NN * HD];
__device__ __nv_bfloat16 g_alo[(size_t)NN * HD];
__device__ __nv_bfloat16 g_x0hi[(size_t)NN * 64];
__device__ __nv_bfloat16 g_x0lo[(size_t)NN * 64];
__device__ __nv_bfloat16 g_wt0[2 * 2 * 192 * 64];        // [mat][split][192n * 64k]
__device__ __nv_bfloat16 g_wtl[3 * 2 * 2 * 192 * 192];   // [l][mat][split][192n * 192k]
__device__ int   g_deg[NN + 1];
__device__ int   g_rowptr[NN + 1];
__device__ int   g_csrsrc[EE];
__device__ int   g_bsum[128];
__device__ int   g_bsumx[128];
__device__ int   g_cnt[GG];
__device__ int   g_gstart[GG + 1];
__device__ float g_stats[NL * 2 * HD];
__device__ float g_affine[2 * HD];
__device__ float g_pool[(size_t)GG * HD];
__device__ float g_t1[(size_t)GG * HD];
__device__ float g_t2[(size_t)GG * HD];

// ---------------- PTX helpers ----------------------------------------------
__device__ __forceinline__ uint32_t smem_u32(const void* p) {
    uint32_t a;
    asm("{ .reg .u64 t; cvta.to.shared.u64 t, %1; cvt.u32.u64 %0, t; }"
        : "=r"(a) : "l"(p));
    return a;
}

__device__ __forceinline__ void mma_bf16(float* d, const uint32_t* a, const uint32_t* b) {
    asm volatile(
        "mma.sync.aligned.m16n8k16.row.col.f32.bf16.bf16.f32 "
        "{%0,%1,%2,%3}, {%4,%5,%6,%7}, {%8,%9}, {%0,%1,%2,%3};"
        : "+f"(d[0]), "+f"(d[1]), "+f"(d[2]), "+f"(d[3])
        : "r"(a[0]), "r"(a[1]), "r"(a[2]), "r"(a[3]), "r"(b[0]), "r"(b[1]));
}

#define LDSM4(r, addr) \
    asm volatile("ldmatrix.sync.aligned.m8n8.x4.shared.b16 {%0,%1,%2,%3}, [%4];" \
                 : "=r"((r)[0]), "=r"((r)[1]), "=r"((r)[2]), "=r"((r)[3]) : "r"(addr))

__device__ __forceinline__ void cpa16(uint32_t dst, const void* src, int srcBytes) {
    asm volatile("cp.async.cg.shared.global [%0], [%1], 16, %2;"
                 :: "r"(dst), "l"(src), "r"(srcBytes) : "memory");
}
#define CP_COMMIT() asm volatile("cp.async.commit_group;" ::: "memory")
#define CP_WAIT(n)  asm volatile("cp.async.wait_group %0;" :: "n"(n) : "memory")

// ======= GEMM variant 1: streaming, M64xN192, for L0 (K=32) ================
__global__ __launch_bounds__(256, 2) void k_mma_s(
    const __nv_bfloat16* __restrict__ Xhi, const __nv_bfloat16* __restrict__ Xlo,
    int ldA, int K, int M,
    const __nv_bfloat16* __restrict__ B0, const __nv_bfloat16* __restrict__ B1,
    int ldB, const float* __restrict__ bias,
    float* __restrict__ O1, float* __restrict__ O2)
{
    extern __shared__ __nv_bfloat16 sm[];
    const int chunk = (K < 32) ? K : 32;
    const int S = chunk + 8;
    const int tid = threadIdx.x, lane = tid & 31, wid = tid >> 5;
    const int warpM = wid & 1, warpN = wid >> 1;
    const int row0 = blockIdx.x * 64;
    const int mat = blockIdx.y;
    const __nv_bfloat16* Bbase = mat ? B1 : B0;
    const size_t splitOffB = (size_t)192 * ldB;

    const uint32_t sb = smem_u32(sm);
    const uint32_t offAlo   = 64 * S * 2;
    const uint32_t offBh    = 128 * S * 2;
    const uint32_t offBlo   = 192 * S * 2;
    const uint32_t stageSz  = (128 + 384) * S * 2;

    float d[2][6][4];
#pragma unroll
    for (int a = 0; a < 2; a++)
#pragma unroll
        for (int b = 0; b < 6; b++)
#pragma unroll
            for (int c = 0; c < 4; c++) d[a][b][c] = 0.f;

    const uint32_t aAddr = sb +
        (((warpM * 32 + (lane & 15)) * S + ((lane >> 4) * 8)) * 2);
    const uint32_t bAddr = sb + offBh +
        (((warpN * 48 + (lane & 7) + ((lane >> 4) << 3)) * S + (((lane >> 3) & 1) * 8)) * 2);
    const uint32_t step16 = 16 * S * 2;

    const int cv = chunk >> 3;
    const int nChunks = K / chunk;

    auto load_chunk = [&](int c, int stage) {
        const uint32_t st = sb + stage * stageSz;
        const int kc = c * chunk;
        for (int idx = tid; idx < 64 * cv; idx += 256) {
            const int rr = idx / cv, kv = idx % cv;
            const int row = row0 + rr;
            const int ok = (row < M) ? 16 : 0;
            const size_t so = (size_t)(ok ? row : 0) * ldA + kc + kv * 8;
            const uint32_t doff = (rr * S + kv * 8) * 2;
            cpa16(st + doff, Xhi + so, ok);
            cpa16(st + offAlo + doff, Xlo + so, ok);
        }
        for (int idx = tid; idx < 192 * cv; idx += 256) {
            const int nn = idx / cv, kv = idx % cv;
            const __nv_bfloat16* src = Bbase + (size_t)nn * ldB + kc + kv * 8;
            const uint32_t doff = (nn * S + kv * 8) * 2;
            cpa16(st + offBh + doff, src, 16);
            cpa16(st + offBh + offBlo + doff, src + splitOffB, 16);
        }
        CP_COMMIT();
    };

    load_chunk(0, 0);

    for (int c = 0; c < nChunks; c++) {
        const int stage = c & 1;
        if (c + 1 < nChunks) { load_chunk(c + 1, stage ^ 1); CP_WAIT(1); }
        else                 { CP_WAIT(0); }
        __syncthreads();

        const uint32_t so = stage * stageSz;
        const int nk = chunk >> 4;
        for (int ks = 0; ks < nk; ks++) {
            const uint32_t kb = (uint32_t)ks * 32;
            uint32_t ah0[4], al0[4], ah1[4], al1[4];
            LDSM4(ah0, aAddr + so + kb);
            LDSM4(al0, aAddr + so + kb + offAlo);
            LDSM4(ah1, aAddr + so + kb + step16);
            LDSM4(al1, aAddr + so + kb + step16 + offAlo);
#pragma unroll
            for (int p = 0; p < 3; p++) {
                uint32_t bh4[4], bl4[4];
                LDSM4(bh4, bAddr + so + kb + p * step16);
                LDSM4(bl4, bAddr + so + kb + p * step16 + offBlo);
#pragma unroll
                for (int hh = 0; hh < 2; hh++) {
                    const int nj = p * 2 + hh;
                    const uint32_t* b_h = &bh4[hh * 2];
                    const uint32_t* b_l = &bl4[hh * 2];
                    mma_bf16(d[0][nj], ah0, b_h);
                    mma_bf16(d[0][nj], ah0, b_l);
                    mma_bf16(d[0][nj], al0, b_h);
                    mma_bf16(d[1][nj], ah1, b_h);
                    mma_bf16(d[1][nj], ah1, b_l);
                    mma_bf16(d[1][nj], al1, b_h);
                }
            }
        }
        __syncthreads();
    }

    const int r = lane >> 2, cq = lane & 3;
    float* O = mat ? O2 : O1;
#pragma unroll
    for (int nj = 0; nj < 6; nj++) {
        const int col = warpN * 48 + nj * 8 + cq * 2;
        float b0 = 0.f, b1v = 0.f;
        if (mat == 0 && bias) { b0 = bias[col]; b1v = bias[col + 1]; }
#pragma unroll
        for (int mi = 0; mi < 2; mi++) {
            const int rr = row0 + warpM * 32 + mi * 16 + r;
            if (rr < M) {
                float2 v = make_float2(d[mi][nj][0] + b0, d[mi][nj][1] + b1v);
                *(float2*)(&O[(size_t)rr * HD + col]) = v;
            }
            if (rr + 8 < M) {
                float2 v = make_float2(d[mi][nj][2] + b0, d[mi][nj][3] + b1v);
                *(float2*)(&O[(size_t)(rr + 8) * HD + col]) = v;
            }
        }
    }
}

// ======= GEMM variant 2: B-resident + cross-tile prefetch (K=192) ===========
__global__ __launch_bounds__(256, 2) void k_mma_b(
    const __nv_bfloat16* __restrict__ Xhi, const __nv_bfloat16* __restrict__ Xlo,
    int ldA, int K, int M,
    const __nv_bfloat16* __restrict__ B0, const __nv_bfloat16* __restrict__ B1,
    int ldB, const float* __restrict__ bias,
    float* __restrict__ O1, float* __restrict__ O2)
{
    extern __shared__ __nv_bfloat16 sm[];
    const int chunk = (K < 32) ? K : 32;
    const int S = chunk + 8;
    const int SB = K + 8;
    const int tid = threadIdx.x, lane = tid & 31, wid = tid >> 5;
    const int warpM = wid & 3, warpN = wid >> 2;
    const int mat = blockIdx.y >> 1;
    const int ncol0 = (blockIdx.y & 1) * 96;
    const __nv_bfloat16* Bbase = mat ? B1 : B0;
    const size_t splitOffB = (size_t)192 * ldB;

    const uint32_t sb = smem_u32(sm);
    const uint32_t offAlo   = 64 * S * 2;
    const uint32_t stageSz  = 128 * S * 2;
    const uint32_t offB     = 2 * stageSz;
    const uint32_t offBlo   = (uint32_t)(96 * SB * 2);

    // ---- B resident load (once) ----
    const int KV = K >> 3;
    for (int idx = tid; idx < 96 * KV; idx += 256) {
        const int nn = idx / KV, kv = idx % KV;
        const __nv_bfloat16* src = Bbase + (size_t)(ncol0 + nn) * ldB + kv * 8;
        const uint32_t doff = (uint32_t)((nn * SB + kv * 8) * 2);
        cpa16(sb + offB + doff, src, 16);
        cpa16(sb + offB + offBlo + doff, src + splitOffB, 16);
    }
    CP_COMMIT();

    const uint32_t aAddr = sb +
        (((warpM * 16 + (lane & 15)) * S + ((lane >> 4) * 8)) * 2);
    const uint32_t bAddr = sb + offB +
        (uint32_t)((((warpN * 48 + (lane & 7) + ((lane >> 4) << 3)) * SB) +
                    (((lane >> 3) & 1) * 8)) * 2);
    const uint32_t bStep16 = (uint32_t)(16 * SB * 2);

    const int cv = chunk >> 3;
    const int nChunks = K / chunk;     // 6 (even -> chunk0 always stage 0)
    const int nTiles = (M + 63) >> 6;

    const int r = lane >> 2, cq = lane & 3;
    float* O = mat ? O2 : O1;

    auto loadA = [&](int row0, int c, int stage) {
        const uint32_t st = sb + stage * stageSz;
        const int kc = c * chunk;
        for (int idx = tid; idx < 64 * cv; idx += 256) {
            const int rr = idx / cv, kv = idx % cv;
            const int row = row0 + rr;
            const int ok = (row < M) ? 16 : 0;
            const size_t so = (size_t)(ok ? row : 0) * ldA + kc + kv * 8;
            const uint32_t doff = (rr * S + kv * 8) * 2;
            cpa16(st + doff, Xhi + so, ok);
            cpa16(st + offAlo + doff, Xlo + so, ok);
        }
        CP_COMMIT();
    };

    int first = 1;
    for (int mt = blockIdx.x; mt < nTiles; mt += gridDim.x) {
        const int row0 = mt * 64;

        float d[6][4];
#pragma unroll
        for (int b = 0; b < 6; b++)
#pragma unroll
            for (int c = 0; c < 4; c++) d[b][c] = 0.f;

        if (first) { loadA(row0, 0, 0); first = 0; }   // else: prefetched

        for (int c = 0; c < nChunks; c++) {
            const int stage = c & 1;
            int issued = 0;
            if (c + 1 < nChunks) {
                loadA(row0, c + 1, stage ^ 1);
                issued = 1;
            } else {
                const int nmt = mt + gridDim.x;
                if (nmt < nTiles) { loadA(nmt * 64, 0, stage ^ 1); issued = 1; }
            }
            if (issued) CP_WAIT(1); else CP_WAIT(0);
            __syncthreads();

            const uint32_t so = stage * stageSz;
            const int nk = chunk >> 4;
            for (int ks = 0; ks < nk; ks++) {
                const uint32_t kbA = (uint32_t)ks * 32;
                const uint32_t kcol = (uint32_t)((c * chunk + ks * 16) * 2);
                uint32_t ah[4], al[4];
                LDSM4(ah, aAddr + so + kbA);
                LDSM4(al, aAddr + so + kbA + offAlo);
#pragma unroll
                for (int p = 0; p < 3; p++) {
                    uint32_t bh4[4], bl4[4];
                    LDSM4(bh4, bAddr + kcol + p * bStep16);
                    LDSM4(bl4, bAddr + kcol + p * bStep16 + offBlo);
#pragma unroll
                    for (int hh = 0; hh < 2; hh++) {
                        const int nj = p * 2 + hh;
                        const uint32_t* b_h = &bh4[hh * 2];
                        const uint32_t* b_l = &bl4[hh * 2];
                        mma_bf16(d[nj], ah, b_h);
                        mma_bf16(d[nj], ah, b_l);
                        mma_bf16(d[nj], al, b_h);
                    }
                }
            }
            __syncthreads();
        }

#pragma unroll
        for (int nj = 0; nj < 6; nj++) {
            const int col = ncol0 + warpN * 48 + nj * 8 + cq * 2;
            float b0 = 0.f, b1v = 0.f;
            if (mat == 0 && bias) { b0 = bias[col]; b1v = bias[col + 1]; }
            const int rr = row0 + warpM * 16 + r;
            if (rr < M) {
                float2 v = make_float2(d[nj][0] + b0, d[nj][1] + b1v);
                *(float2*)(&O[(size_t)rr * HD + col]) = v;
            }
            if (rr + 8 < M) {
                float2 v = make_float2(d[nj][2] + b0, d[nj][3] + b1v);
                *(float2*)(&O[(size_t)(rr + 8) * HD + col]) = v;
            }
        }
    }
}

// ---------------- weight / activation prep ----------------------------------
__device__ __forceinline__ void split_bf16(float v, __nv_bfloat16& h, __nv_bfloat16& l) {
    h = __float2bfloat16(v);
    l = __float2bfloat16(v - __bfloat162float(h));
}
__device__ __forceinline__ uint32_t pk_bf16(__nv_bfloat16 a, __nv_bfloat16 b) {
    __nv_bfloat162 t(a, b);
    return *reinterpret_cast<uint32_t*>(&t);
}

__global__ void k_prep_w(const float* __restrict__ Wrel0, const float* __restrict__ Wroot0,
                         const float* __restrict__ Wrel, const float* __restrict__ Wroot,
                         __nv_bfloat16* wt0, __nv_bfloat16* wtl)
{
    int i = blockIdx.x * blockDim.x + threadIdx.x;
    if (i < 2 * 192 * 64) {
        int mat = i / (192 * 64), r = i % (192 * 64);
        int n = r / 64, k = r % 64;
        const float* W = mat ? Wroot0 : Wrel0;
        float v = (k < IND) ? W[k * HD + n] : 0.f;
        __nv_bfloat16 h, l; split_bf16(v, h, l);
        wt0[mat * (2 * 192 * 64) + r] = h;
        wt0[mat * (2 * 192 * 64) + 192 * 64 + r] = l;
    }
    if (i < 3 * 2 * 192 * 192) {
        int ly = i / (2 * 192 * 192), r1 = i % (2 * 192 * 192);
        int mat = r1 / (192 * 192), r = r1 % (192 * 192);
        int n = r / 192, k = r % 192;
        const float* W = (mat ? Wroot : Wrel) + (size_t)ly * HD * HD;
        float v = W[k * HD + n];
        __nv_bfloat16 h, l; split_bf16(v, h, l);
        wtl[(size_t)((ly * 2 + mat) * 2 + 0) * (192 * 192) + r] = h;
        wtl[(size_t)((ly * 2 + mat) * 2 + 1) * (192 * 192) + r] = l;
    }
}

// input split + zero deg/cnt/stats (folded zero_csr)
__global__ void k_conv_x0(const float* __restrict__ x,
                          __nv_bfloat16* __restrict__ xhi, __nv_bfloat16* __restrict__ xlo,
                          int* deg, int* cnt, float* stats)
{
    size_t i = (size_t)blockIdx.x * blockDim.x + threadIdx.x;
    if (i < NN) deg[i] = 0;
    if (i < GG) cnt[i] = 0;
    if (i < NL * 2 * HD) stats[i] = 0.f;
    if (i >= (size_t)NN * 8) return;
    const int row = (int)(i >> 3), oct = (int)(i & 7);
    __nv_bfloat16 h[8], l[8];
    if (oct < 4) {
        const float4 v0 = *(const float4*)(x + (size_t)row * IND + oct * 8);
        const float4 v1 = *(const float4*)(x + (size_t)row * IND + oct * 8 + 4);
        split_bf16(v0.x, h[0], l[0]); split_bf16(v0.y, h[1], l[1]);
        split_bf16(v0.z, h[2], l[2]); split_bf16(v0.w, h[3], l[3]);
        split_bf16(v1.x, h[4], l[4]); split_bf16(v1.y, h[5], l[5]);
        split_bf16(v1.z, h[6], l[6]); split_bf16(v1.w, h[7], l[7]);
    } else {
#pragma unroll
        for (int k = 0; k < 8; k++) { h[k] = __float2bfloat16(0.f); l[k] = h[k]; }
    }
    uint4 hv = make_uint4(pk_bf16(h[0], h[1]), pk_bf16(h[2], h[3]),
                          pk_bf16(h[4], h[5]), pk_bf16(h[6], h[7]));
    uint4 lv = make_uint4(pk_bf16(l[0], l[1]), pk_bf16(l[2], l[3]),
                          pk_bf16(l[4], l[5]), pk_bf16(l[6], l[7]));
    *(uint4*)(xhi + (size_t)row * 64 + oct * 8) = hv;
    *(uint4*)(xlo + (size_t)row * 64 + oct * 8) = lv;
}

// relu(a*h + b) -> bf16 hi/lo (affine precomputed)
__global__ void k_act_conv(const float* __restrict__ h, const float* __restrict__ affine,
                           __nv_bfloat16* __restrict__ ahi, __nv_bfloat16* __restrict__ alo)
{
    size_t i = (size_t)blockIdx.x * blockDim.x + threadIdx.x;
    if (i >= (size_t)NN * 48) return;
    const int f4 = (int)(i % 48);
    const float4 v  = *(const float4*)(h + i * 4);
    const float4 a4 = *(const float4*)(affine + f4 * 4);
    const float4 b4 = *(const float4*)(affine + HD + f4 * 4);
    float x0 = fmaxf(fmaf(v.x, a4.x, b4.x), 0.f);
    float x1 = fmaxf(fmaf(v.y, a4.y, b4.y), 0.f);
    float x2 = fmaxf(fmaf(v.z, a4.z, b4.z), 0.f);
    float x3 = fmaxf(fmaf(v.w, a4.w, b4.w), 0.f);
    __nv_bfloat16 h0, h1, h2, h3, l0, l1, l2, l3;
    split_bf16(x0, h0, l0); split_bf16(x1, h1, l1);
    split_bf16(x2, h2, l2); split_bf16(x3, h3, l3);
    *(uint2*)(ahi + i * 4) = make_uint2(pk_bf16(h0, h1), pk_bf16(h2, h3));
    *(uint2*)(alo + i * 4) = make_uint2(pk_bf16(l0, l1), pk_bf16(l2, l3));
}

// ---------------- CSR build ---------------------------------------------------
__global__ void k_count(const int* __restrict__ dst, const int* __restrict__ batch,
                        int* deg, int* cnt) {
    int i = blockIdx.x * blockDim.x + threadIdx.x;
    if (i < EE) atomicAdd(&deg[dst[i]], 1);
    if (i < NN) atomicAdd(&cnt[batch[i]], 1);
}
__global__ void k_scan_block(const int* __restrict__ in, int* rowptr, int* bsum) {
    __shared__ int s[1024];
    int t = threadIdx.x;
    int i = blockIdx.x * 1024 + t;
    int v = (i < NN) ? in[i] : 0;
    s[t] = v;
    __syncthreads();
#pragma unroll
    for (int off = 1; off < 1024; off <<= 1) {
        int add = (t >= off) ? s[t - off] : 0;
        __syncthreads();
        s[t] += add;
        __syncthreads();
    }
    if (i < NN) rowptr[i + 1] = s[t];
    if (t == 1023) bsum[blockIdx.x] = s[1023];
}
__global__ void k_scan_single(const int* __restrict__ in, int* out, int n, int writeTotal) {
    __shared__ int s[1024];
    __shared__ int carry;
    int t = threadIdx.x;
    if (t == 0) carry = 0;
    __syncthreads();
    for (int c0 = 0; c0 < n; c0 += 1024) {
        int v = (c0 + t < n) ? in[c0 + t] : 0;
        s[t] = v;
        __syncthreads();
#pragma unroll
        for (int off = 1; off < 1024; off <<= 1) {
            int add = (t >= off) ? s[t - off] : 0;
            __syncthreads();
            s[t] += add;
            __syncthreads();
        }
        if (c0 + t < n) out[c0 + t] = carry + s[t] - v;
        __syncthreads();
        if (t == 1023) carry += s[1023];
        __syncthreads();
    }
    if (t == 0 && writeTotal) out[n] = carry;
}
// fix rowptr (add block prefix) AND write the fill cursor (folded copy_cursor)
__global__ void k_scan_fix(int* rowptr, const int* __restrict__ bsumx, int* cursor) {
    int i = blockIdx.x * 1024 + threadIdx.x;
    if (i < NN) {
        const int v = rowptr[i + 1] + bsumx[blockIdx.x];
        rowptr[i + 1] = v;
        if (i + 1 < NN) cursor[i + 1] = v;
    }
    if (i == 0) { rowptr[0] = 0; cursor[0] = 0; }
}
__global__ void k_fill(const int* __restrict__ src, const int* __restrict__ dst,
                       int* cursor, int* csrsrc) {
    int i = blockIdx.x * blockDim.x + threadIdx.x;
    if (i < EE) {
        int slot = atomicAdd(&cursor[dst[i]], 1);
        csrsrc[slot] = src[i];
    }
}

// ---------------- fused aggregate + BN stats (float2, 96-thr warp-aligned) ---
__global__ __launch_bounds__(192) void k_aggstats(
    const float* __restrict__ relf, const float* __restrict__ rootf,
    const int* __restrict__ rowptr, const int* __restrict__ csrsrc,
    float* __restrict__ hf, float* __restrict__ stats)
{
    const float2* rel2  = (const float2*)relf;
    const float2* root2 = (const float2*)rootf;
    float2* h2 = (float2*)hf;
    const int g  = threadIdx.x / 96;
    const int f2 = threadIdx.x % 96;
    float s0 = 0.f, s1 = 0.f, q0 = 0.f, q1 = 0.f;
    const int stride = gridDim.x * 2;
    for (int n = blockIdx.x * 2 + g; n < NN; n += stride) {
        const int st = __ldg(&rowptr[n]), en = __ldg(&rowptr[n + 1]);
        float2 acc = root2[(size_t)n * 96 + f2];
        int i = st;
        for (; i + 4 <= en; i += 4) {
            const int a0 = __ldg(&csrsrc[i]);
            const int a1 = __ldg(&csrsrc[i + 1]);
            const int a2 = __ldg(&csrsrc[i + 2]);
            const int a3 = __ldg(&csrsrc[i + 3]);
            const float2 v0 = rel2[(size_t)a0 * 96 + f2];
            const float2 v1 = rel2[(size_t)a1 * 96 + f2];
            const float2 v2 = rel2[(size_t)a2 * 96 + f2];
            const float2 v3 = rel2[(size_t)a3 * 96 + f2];
            acc.x += (v0.x + v1.x) + (v2.x + v3.x);
            acc.y += (v0.y + v1.y) + (v2.y + v3.y);
        }
        for (; i < en; i++) {
            const int a0 = __ldg(&csrsrc[i]);
            const float2 v0 = rel2[(size_t)a0 * 96 + f2];
            acc.x += v0.x; acc.y += v0.y;
        }
        h2[(size_t)n * 96 + f2] = acc;
        s0 += acc.x; q0 += acc.x * acc.x;
        s1 += acc.y; q1 += acc.y * acc.y;
    }
    const int f = f2 * 2;
    atomicAdd(&stats[f + 0], s0);
    atomicAdd(&stats[f + 1], s1);
    atomicAdd(&stats[HD + f + 0], q0);
    atomicAdd(&stats[HD + f + 1], q1);
}

__global__ void k_bn_finalize(const float* __restrict__ gamma, const float* __restrict__ beta,
                              int l, const float* __restrict__ stats, float* __restrict__ affine)
{
    int f = threadIdx.x;
    float mu = stats[f] / (float)NN;
    float var = stats[HD + f] / (float)NN - mu * mu;
    float a = gamma[l * HD + f] * rsqrtf(var + EPSV);
    affine[f] = a;
    affine[HD + f] = fmaf(-mu, a, beta[l * HD + f]);
}

// pool with in-kernel BN affine for the last layer (removes one launch)
__global__ void k_pool(const float* __restrict__ h, const int* __restrict__ gstart,
                       const float* __restrict__ stats,
                       const float* __restrict__ gamma, const float* __restrict__ beta,
                       int l, float* __restrict__ out)
{
    int g = blockIdx.x, f = threadIdx.x;
    int s = gstart[g], e = gstart[g + 1];
    const float inv = 1.f / (float)NN;
    const float mu = stats[f] * inv;
    const float var = stats[HD + f] * inv - mu * mu;
    const float a = gamma[l * HD + f] * rsqrtf(var + EPSV);
    const float bb = fmaf(-mu, a, beta[l * HD + f]);
    float acc = 0.f;
    for (int r = s; r < e; r++)
        acc += fmaxf(fmaf(h[(size_t)r * HD + f], a, bb), 0.f);
    int c = e - s;
    out[(size_t)g * HD + f] = acc / (float)(c > 0 ? c : 1);
}

// ---------------- head MLP (FFMA2 path, tiny) ---------------------------------
__device__ __forceinline__ void ffma2(ull& d, ull a, ull b) {
    asm("fma.rn.f32x2 %0, %1, %2, %0;" : "+l"(d) : "l"(a), "l"(b));
}
__device__ __forceinline__ ull pack2(float x) {
    ull r; asm("mov.b64 %0, {%1, %1};" : "=l"(r) : "f"(x)); return r;
}
__device__ __forceinline__ void unpack2(ull v, float& lo, float& hi) {
    asm("mov.b64 {%0, %1}, %2;" : "=f"(lo), "=f"(hi) : "l"(v));
}

__global__ __launch_bounds__(256) void k_gemm_head(
    const float* __restrict__ X, int M,
    const float* __restrict__ W1, const float* __restrict__ b1,
    float* __restrict__ O1, int mode)
{
    __shared__ float Xs[32][65];
    __shared__ float Ws1[32][64];
    const int tid = threadIdx.x;
    const int tx = tid & 15, ty = tid >> 4;
    const int row0 = blockIdx.x * 64, col0 = blockIdx.y * 64;
    ull acc1[4][2];
#pragma unroll
    for (int i = 0; i < 4; i++) { acc1[i][0] = 0ULL; acc1[i][1] = 0ULL; }
    for (int k0 = 0; k0 < HD; k0 += 32) {
#pragma unroll
        for (int i = 0; i < 8; i++) {
            int e = tid + i * 256, m = e >> 5, kk = e & 31;
            int r = row0 + m;
            float v = (r < M) ? X[(size_t)r * HD + (k0 + kk)] : 0.f;
            if (mode == 1) v = fmaxf(v, 0.f);
            Xs[kk][m] = v;
        }
#pragma unroll
        for (int i = 0; i < 8; i++) {
            int e = tid + i * 256, kk = e >> 6, n = e & 63;
            Ws1[kk][n] = W1[(size_t)(k0 + kk) * HD + col0 + n];
        }
        __syncthreads();
#pragma unroll
        for (int k = 0; k < 32; k++) {
            ull xp[4];
#pragma unroll
            for (int i = 0; i < 4; i++) xp[i] = pack2(Xs[k][ty * 4 + i]);
            const ull* w1 = reinterpret_cast<const ull*>(&Ws1[k][tx * 4]);
            ull w1a = w1[0], w1b = w1[1];
#pragma unroll
            for (int i = 0; i < 4; i++) { ffma2(acc1[i][0], xp[i], w1a); ffma2(acc1[i][1], xp[i], w1b); }
        }
        __syncthreads();
    }
    const int c = col0 + tx * 4;
    float bb0 = b1[c], bb1 = b1[c + 1], bb2 = b1[c + 2], bb3 = b1[c + 3];
#pragma unroll
    for (int i = 0; i < 4; i++) {
        int r = row0 + ty * 4 + i;
        if (r >= M) break;
        float4 o;
        unpack2(acc1[i][0], o.x, o.y);
        unpack2(acc1[i][1], o.z, o.w);
        o.x += bb0; o.y += bb1; o.z += bb2; o.w += bb3;
        *reinterpret_cast<float4*>(&O1[(size_t)r * HD + c]) = o;
    }
}

__global__ void k_out(const float* __restrict__ h2, const float* __restrict__ Wout,
                      const float* __restrict__ bout, float* __restrict__ out)
{
    int gid = blockIdx.x * blockDim.x + threadIdx.x;
    int lane = gid & 31, g = gid >> 5;
    if (g >= GG) return;
    float acc = 0.f;
#pragma unroll
    for (int k = lane; k < HD; k += 32)
        acc += h2[(size_t)g * HD + k] * Wout[k];
#pragma unroll
    for (int off = 16; off; off >>= 1)
        acc += __shfl_down_sync(0xffffffffu, acc, off);
    if (lane == 0) out[g] = acc + bout[0];
}

// ---------------- launch --------------------------------------------------------
extern "C" void kernel_launch(void* const* d_in, const int* in_sizes, int n_in,
                              void* d_out, int out_size)
{
    const float* x        = (const float*)d_in[0];
    const int*   edge_src = (const int*)d_in[1];
    const int*   edge_dst = (const int*)d_in[2];
    const int*   batch    = (const int*)d_in[3];
    const float* Wrel0    = (const float*)d_in[4];
    const float* brel0    = (const float*)d_in[5];
    const float* Wroot0   = (const float*)d_in[6];
    const float* Wrel     = (const float*)d_in[7];
    const float* brel     = (const float*)d_in[8];
    const float* Wroot    = (const float*)d_in[9];
    const float* gamma    = (const float*)d_in[10];
    const float* beta     = (const float*)d_in[11];
    const float* Wh1      = (const float*)d_in[12];
    const float* bh1      = (const float*)d_in[13];
    const float* Wh2      = (const float*)d_in[14];
    const float* bh2      = (const float*)d_in[15];
    const float* Wout     = (const float*)d_in[16];
    const float* bout     = (const float*)d_in[17];
    float* out = (float*)d_out;

    float *p_h, *p_rel, *p_agg, *p_stats, *p_affine, *p_pool, *p_t1, *p_t2;
    int *p_deg, *p_rowptr, *p_csrsrc, *p_bsum, *p_bsumx, *p_cnt, *p_gstart;
    __nv_bfloat16 *p_ahi, *p_alo, *p_x0hi, *p_x0lo, *p_wt0, *p_wtl;
    cudaGetSymbolAddress((void**)&p_h, g_h);
    cudaGetSymbolAddress((void**)&p_rel, g_rel);
    cudaGetSymbolAddress((void**)&p_agg, g_agg);
    cudaGetSymbolAddress((void**)&p_deg, g_deg);
    cudaGetSymbolAddress((void**)&p_rowptr, g_rowptr);
    cudaGetSymbolAddress((void**)&p_csrsrc, g_csrsrc);
    cudaGetSymbolAddress((void**)&p_bsum, g_bsum);
    cudaGetSymbolAddress((void**)&p_bsumx, g_bsumx);
    cudaGetSymbolAddress((void**)&p_cnt, g_cnt);
    cudaGetSymbolAddress((void**)&p_gstart, g_gstart);
    cudaGetSymbolAddress((void**)&p_stats, g_stats);
    cudaGetSymbolAddress((void**)&p_affine, g_affine);
    cudaGetSymbolAddress((void**)&p_pool, g_pool);
    cudaGetSymbolAddress((void**)&p_t1, g_t1);
    cudaGetSymbolAddress((void**)&p_t2, g_t2);
    cudaGetSymbolAddress((void**)&p_ahi, g_ahi);
    cudaGetSymbolAddress((void**)&p_alo, g_alo);
    cudaGetSymbolAddress((void**)&p_x0hi, g_x0hi);
    cudaGetSymbolAddress((void**)&p_x0lo, g_x0lo);
    cudaGetSymbolAddress((void**)&p_wt0, g_wt0);
    cudaGetSymbolAddress((void**)&p_wtl, g_wtl);

    const int smemS = 2 * 512 * 40 * 2;                 // 81920
    const int smemB = 20480 + 2 * 96 * (192 + 8) * 2;   // 97280
    cudaFuncSetAttribute(k_mma_s, cudaFuncAttributeMaxDynamicSharedMemorySize, smemS);
    cudaFuncSetAttribute(k_mma_b, cudaFuncAttributeMaxDynamicSharedMemorySize, smemB);

    const int nbScan = (NN + 1023) / 1024;

    // ---- prep (conv_x0 also zeros deg/cnt/stats) ----
    k_conv_x0<<<(NN * 8 + 255) / 256, 256>>>(x, p_x0hi, p_x0lo, p_deg, p_cnt, p_stats);
    k_prep_w<<<(3 * 2 * 192 * 192 + 255) / 256, 256>>>(Wrel0, Wroot0, Wrel, Wroot, p_wt0, p_wtl);
    k_mma_s<<<dim3((NN + 63) / 64, 2), 256, smemS>>>(p_x0hi, p_x0lo, 64, 32, NN,
                                                     p_wt0, p_wt0 + 2 * 192 * 64, 64,
                                                     brel0, p_rel, p_agg);

    // ---- CSR build ----
    k_count<<<(EE + 255) / 256, 256>>>(edge_dst, batch, p_deg, p_cnt);
    k_scan_block<<<nbScan, 1024>>>(p_deg, p_rowptr, p_bsum);
    k_scan_single<<<1, 1024>>>(p_bsum, p_bsumx, nbScan, 0);
    k_scan_fix<<<nbScan, 1024>>>(p_rowptr, p_bsumx, p_deg);
    k_fill<<<(EE + 255) / 256, 256>>>(edge_src, edge_dst, p_deg, p_csrsrc);

    // ---- GNN layers ----
    for (int l = 0; l < NL; l++) {
        if (l > 0) {
            const __nv_bfloat16* B0 = p_wtl + (size_t)(l - 1) * 4 * 192 * 192;
            const __nv_bfloat16* B1 = B0 + 2 * 192 * 192;
            k_mma_b<<<dim3(148, 4), 256, smemB>>>(p_ahi, p_alo, HD, HD, NN,
                                                  B0, B1, HD,
                                                  brel + (size_t)(l - 1) * HD, p_rel, p_agg);
        }
        k_aggstats<<<1184, 192>>>(p_rel, p_agg, p_rowptr, p_csrsrc, p_h,
                                  p_stats + (size_t)l * 2 * HD);
        if (l < NL - 1) {
            k_bn_finalize<<<1, HD>>>(gamma, beta, l, p_stats + (size_t)l * 2 * HD, p_affine);
            k_act_conv<<<(NN * 48 + 255) / 256, 256>>>(p_h, p_affine, p_ahi, p_alo);
        }
    }

    // ---- pooling (computes last BN affine in-kernel + relu) ----
    k_scan_single<<<1, 1024>>>(p_cnt, p_gstart, GG, 1);
    k_pool<<<GG, HD>>>(p_h, p_gstart, p_stats + (size_t)(NL - 1) * 2 * HD,
                       gamma, beta, NL - 1, p_pool);

    // ---- head MLP ----
    dim3 hgrid((GG + 63) / 64, HD / 64);
    k_gemm_head<<<hgrid, 256>>>(p_pool, GG, Wh1, bh1, p_t1, 0);
    k_gemm_head<<<hgrid, 256>>>(p_t1, GG, Wh2, bh2, p_t2, 1);
    k_out<<<(GG * 32 + 255) / 256, 256>>>(p_t2, Wout, bout, out);
}